// round 4
// baseline (speedup 1.0000x reference)
#include <cuda_runtime.h>
#include <cstdint>

// ---------------------------------------------------------------------------
// Relative attention — tf32 mma GEMMs (cp.async double-buffered) + fused
// flash attention with pipelined K/V/bias loads.
// ---------------------------------------------------------------------------

namespace {
constexpr int BATCH = 32;
constexpr int NH    = 8;
constexpr int NTOK  = 577;
constexpr int DIM   = 512;
constexpr int DH    = 64;
constexpr int BH    = BATCH * NH;        // 256
constexpr int MROWS = BATCH * NTOK;      // 18464
constexpr int BPAD  = 640;               // padded bias row stride
constexpr float SCALE = 0.125f;
constexpr float LOG2E = 1.4426950408889634f;
}

// Scratch (device globals: allocation-free contract)
__device__ float g_q[BH * NTOK * DH];
__device__ float g_k[BH * NTOK * DH];
__device__ float g_v[BH * NTOK * DH];
__device__ float g_biasp[NH * NTOK * BPAD];     // 11.8 MB, cols>=577 = -1e30
__device__ float g_attn[MROWS * DIM];

// ---------------------------------------------------------------------------
__device__ __forceinline__ float to_tf32(float x) {
    unsigned u;
    asm("cvt.rna.tf32.f32 %0, %1;" : "=r"(u) : "f"(x));
    return __uint_as_float(u);
}

__device__ __forceinline__ void mma8(float* d, const float* a, const float* b) {
    asm volatile(
        "mma.sync.aligned.m16n8k8.row.col.f32.tf32.tf32.f32 "
        "{%0,%1,%2,%3},{%4,%5,%6,%7},{%8,%9},{%0,%1,%2,%3};"
        : "+f"(d[0]), "+f"(d[1]), "+f"(d[2]), "+f"(d[3])
        : "r"(__float_as_uint(a[0])), "r"(__float_as_uint(a[1])),
          "r"(__float_as_uint(a[2])), "r"(__float_as_uint(a[3])),
          "r"(__float_as_uint(b[0])), "r"(__float_as_uint(b[1])));
}

__device__ __forceinline__ void cp16(float* dst, const float* src) {
    unsigned d = (unsigned)__cvta_generic_to_shared(dst);
    asm volatile("cp.async.cg.shared.global [%0], [%1], 16;\n" :: "r"(d), "l"(src));
}
__device__ __forceinline__ void cp_commit() {
    asm volatile("cp.async.commit_group;\n" ::);
}
template <int N>
__device__ __forceinline__ void cp_wait() {
    asm volatile("cp.async.wait_group %0;\n" :: "n"(N));
}

// ---------------------------------------------------------------------------
// Bias expand: g_biasp[h][n][c] = table[rel[n][c]][h] for c<577, else -1e30.
// ---------------------------------------------------------------------------
__global__ void bias_expand(const float* __restrict__ table,
                            const int* __restrict__ rel) {
    int idx = blockIdx.x * 256 + threadIdx.x;
    if (idx >= NTOK * BPAD) return;
    int n = idx / BPAD, c = idx - n * BPAD;
    if (c < NTOK) {
        int r = rel[n * NTOK + c];
#pragma unroll
        for (int h = 0; h < NH; ++h)
            g_biasp[((size_t)h * NTOK + n) * BPAD + c] = table[r * NH + h];
    } else {
#pragma unroll
        for (int h = 0; h < NH; ++h)
            g_biasp[((size_t)h * NTOK + n) * BPAD + c] = -1e30f;
    }
}

// ---------------------------------------------------------------------------
// tf32 NT GEMM, 128x128x32 tile, cp.async double-buffered, 2 blocks/SM.
// MODE 0: A=x, B=qkv_w, scatter into g_q/g_k/g_v.  MODE 1: A=g_attn, B=proj_w.
// ---------------------------------------------------------------------------
namespace {
constexpr int GSTAGE = 2 * 128 * 36;                 // floats per stage (A+B)
constexpr int GEMM_SMEM = 2 * GSTAGE * 4;            // 73728 bytes
}

template <int MODE>
__global__ __launch_bounds__(256, 2) void gemm_tf32(const float* __restrict__ Ain,
                                                    const float* __restrict__ Bm,
                                                    const float* __restrict__ bias,
                                                    float* __restrict__ Cout) {
    extern __shared__ float smg[];
    const float* A = (MODE == 1) ? g_attn : Ain;
    const int tid = threadIdx.x;
    const int lane = tid & 31, wid = tid >> 5;
    const int g = lane >> 2, t = lane & 3;
    const int m0 = blockIdx.y * 128, n0 = blockIdx.x * 128;
    const int wm = (wid >> 2) * 64, wn = (wid & 3) * 32;

    float acc[4][4][4];
#pragma unroll
    for (int i = 0; i < 4; ++i)
#pragma unroll
        for (int j = 0; j < 4; ++j)
#pragma unroll
            for (int e = 0; e < 4; ++e) acc[i][j][e] = 0.f;

    auto issue = [&](int st, int k0) {
        float* As = smg + st * GSTAGE;
        float* Bs = As + 128 * 36;
#pragma unroll
        for (int it = 0; it < 4; ++it) {
            int v = tid + it * 256;
            int row = v >> 3, c4 = (v & 7) << 2;
            int gm = m0 + row; if (gm > MROWS - 1) gm = MROWS - 1;
            cp16(&As[row * 36 + c4], A + (size_t)gm * DIM + k0 + c4);
            int gn = n0 + row;    // grids exact in N: no clamp needed
            cp16(&Bs[row * 36 + c4], Bm + (size_t)gn * DIM + k0 + c4);
        }
        cp_commit();
    };

    issue(0, 0);
    for (int k0 = 0; k0 < DIM; k0 += 32) {
        const int st = (k0 >> 5) & 1;
        if (k0 + 32 < DIM) { issue(st ^ 1, k0 + 32); cp_wait<1>(); }
        else cp_wait<0>();
        __syncthreads();

        const float* As = smg + st * GSTAGE;
        const float* Bs = As + 128 * 36;
#pragma unroll
        for (int ks = 0; ks < 4; ++ks) {
            const int kd = ks * 8;
            float a[4][4];
#pragma unroll
            for (int mf = 0; mf < 4; ++mf) {
                int mr = wm + mf * 16;
                a[mf][0] = to_tf32(As[(mr + g) * 36 + kd + t]);
                a[mf][1] = to_tf32(As[(mr + g + 8) * 36 + kd + t]);
                a[mf][2] = to_tf32(As[(mr + g) * 36 + kd + t + 4]);
                a[mf][3] = to_tf32(As[(mr + g + 8) * 36 + kd + t + 4]);
            }
#pragma unroll
            for (int nf = 0; nf < 4; ++nf) {
                int nr = wn + nf * 8;
                float b[2] = {to_tf32(Bs[(nr + g) * 36 + kd + t]),
                              to_tf32(Bs[(nr + g) * 36 + kd + t + 4])};
#pragma unroll
                for (int mf = 0; mf < 4; ++mf) mma8(acc[mf][nf], a[mf], b);
            }
        }
        __syncthreads();
    }

    if (MODE == 0) {
#pragma unroll
        for (int mf = 0; mf < 4; ++mf) {
#pragma unroll
            for (int ri = 0; ri < 2; ++ri) {
                int gm = m0 + wm + mf * 16 + g + ri * 8;
                if (gm >= MROWS) continue;
                int b_ = gm / NTOK;
                int n_ = gm - b_ * NTOK;
#pragma unroll
                for (int nf = 0; nf < 4; ++nf) {
#pragma unroll
                    for (int ci = 0; ci < 2; ++ci) {
                        int gn = n0 + wn + nf * 8 + t * 2 + ci;
                        int part = gn >> 9;
                        int rem = gn & 511;
                        int h_ = rem >> 6;
                        int dd = rem & 63;
                        float* dst = (part == 0) ? g_q : (part == 1) ? g_k : g_v;
                        dst[((b_ * NH + h_) * NTOK + n_) * DH + dd] = acc[mf][nf][ri * 2 + ci];
                    }
                }
            }
        }
    } else {
#pragma unroll
        for (int mf = 0; mf < 4; ++mf) {
#pragma unroll
            for (int ri = 0; ri < 2; ++ri) {
                int gm = m0 + wm + mf * 16 + g + ri * 8;
                if (gm >= MROWS) continue;
#pragma unroll
                for (int nf = 0; nf < 4; ++nf) {
                    int cbase = n0 + wn + nf * 8 + t * 2;
                    float2 o;
                    o.x = acc[mf][nf][ri * 2 + 0] + bias[cbase];
                    o.y = acc[mf][nf][ri * 2 + 1] + bias[cbase + 1];
                    *reinterpret_cast<float2*>(Cout + (size_t)gm * DIM + cbase) = o;
                }
            }
        }
    }
}

// ---------------------------------------------------------------------------
// Fused flash attention. 256 thr / 128 q-rows per block, 64-key tiles.
// K/V double-buffered cp.async; bias cp.async waited only at epilogue.
// ---------------------------------------------------------------------------
namespace {
constexpr int QS_OFF = 0;                         // Qs[128][68] (tf32)
constexpr int PS_OFF = QS_OFF + 128 * 68;         // Ps[128][68] (tf32)
constexpr int BB_OFF = PS_OFF + 128 * 68;         // Bb[128][68]
constexpr int KS_OFF = BB_OFF + 128 * 68;         // Ks[2][64][68] (raw fp32)
constexpr int VS_OFF = KS_OFF + 2 * 64 * 68;      // Vs[2][64][72] (raw fp32)
constexpr int FL_SMEM = (VS_OFF + 2 * 64 * 72) * 4;   // 176128 bytes
}

__global__ __launch_bounds__(256) void flash_attn() {
    extern __shared__ float sm[];
    float (*Qs)[68] = reinterpret_cast<float(*)[68]>(sm + QS_OFF);
    float (*Ps)[68] = reinterpret_cast<float(*)[68]>(sm + PS_OFF);
    float (*Bb)[68] = reinterpret_cast<float(*)[68]>(sm + BB_OFF);

    const int bh = blockIdx.y, qt = blockIdx.x;
    const int tid = threadIdx.x;
    const int wid = tid >> 5, lane = tid & 31;
    const int g = lane >> 2, t = lane & 3;
    const float* qb = g_q + (size_t)bh * NTOK * DH;
    const float* kb = g_k + (size_t)bh * NTOK * DH;
    const float* vb = g_v + (size_t)bh * NTOK * DH;
    const float* bp = g_biasp + (size_t)(bh & 7) * NTOK * BPAD;

    auto issueKV = [&](int st, int k0) {
        float* Ks = sm + KS_OFF + st * 64 * 68;
        float* Vs = sm + VS_OFF + st * 64 * 72;
#pragma unroll
        for (int it = 0; it < 4; ++it) {
            int v = tid + it * 256;
            int row = v >> 4, c4 = (v & 15) << 2;
            int gk = k0 + row; if (gk > NTOK - 1) gk = NTOK - 1;   // bias pad masks
            cp16(&Ks[row * 68 + c4], kb + (size_t)gk * DH + c4);
            cp16(&Vs[row * 72 + c4], vb + (size_t)gk * DH + c4);
        }
        cp_commit();
    };

    // prologue: start KV(0); load+convert Q tile
    issueKV(0, 0);
#pragma unroll
    for (int it = 0; it < 8; ++it) {
        int s = tid + it * 256;
        int row = s >> 4, c4 = (s & 15) << 2;
        int gq = qt * 128 + row; if (gq > NTOK - 1) gq = NTOK - 1;
        float4 v = *reinterpret_cast<const float4*>(qb + (size_t)gq * DH + c4);
        float4 tv = make_float4(to_tf32(v.x), to_tf32(v.y), to_tf32(v.z), to_tf32(v.w));
        *reinterpret_cast<float4*>(&Qs[row][c4]) = tv;
    }

    const int q0 = wid * 16;
    const int rowA = qt * 128 + q0 + g;
    const int rowB = rowA + 8;

    float accO[8][4];
#pragma unroll
    for (int df = 0; df < 8; ++df)
#pragma unroll
        for (int e = 0; e < 4; ++e) accO[df][e] = 0.f;
    float m_a = -1e30f, m_b = -1e30f, sum_a = 0.f, sum_b = 0.f;

    for (int kt = 0; kt < 10; ++kt) {
        const int k0 = kt * 64;
        const int st = kt & 1;
        const float* Ks = sm + KS_OFF + st * 64 * 68;
        const float* Vs = sm + VS_OFF + st * 64 * 72;

        // issue bias(kt) then KV(kt+1); groups: [.., B_kt, KV_{kt+1}]
#pragma unroll
        for (int it = 0; it < 8; ++it) {
            int v = tid + it * 256;
            int row = v >> 4, c4 = (v & 15) << 2;
            int gq = qt * 128 + row; if (gq > NTOK - 1) gq = NTOK - 1;
            cp16(&Bb[row][c4], bp + (size_t)gq * BPAD + k0 + c4);
        }
        cp_commit();
        if (kt < 9) issueKV(st ^ 1, k0 + 64);

        if (kt < 9) cp_wait<2>(); else cp_wait<1>();   // KV(kt) ready
        __syncthreads();

        // S = Q K^T
        float S[8][4];
#pragma unroll
        for (int nf = 0; nf < 8; ++nf)
#pragma unroll
            for (int e = 0; e < 4; ++e) S[nf][e] = 0.f;
#pragma unroll
        for (int ks = 0; ks < 8; ++ks) {
            const int kd = ks * 8;
            float a[4] = {Qs[q0 + g][kd + t], Qs[q0 + g + 8][kd + t],
                          Qs[q0 + g][kd + t + 4], Qs[q0 + g + 8][kd + t + 4]};
#pragma unroll
            for (int nf = 0; nf < 8; ++nf) {
                float b[2] = {to_tf32(Ks[(nf * 8 + g) * 68 + kd + t]),
                              to_tf32(Ks[(nf * 8 + g) * 68 + kd + t + 4])};
                mma8(S[nf], a, b);
            }
        }

        if (kt < 9) cp_wait<1>(); else cp_wait<0>();   // bias(kt) ready
        __syncthreads();

        // scale + bias + online softmax
        float ma = -1e30f, mb = -1e30f;
#pragma unroll
        for (int nf = 0; nf < 8; ++nf) {
            int c = nf * 8 + t * 2;
            float2 bA = *reinterpret_cast<const float2*>(&Bb[q0 + g][c]);
            float2 bB = *reinterpret_cast<const float2*>(&Bb[q0 + g + 8][c]);
            S[nf][0] = S[nf][0] * SCALE + bA.x;
            S[nf][1] = S[nf][1] * SCALE + bA.y;
            S[nf][2] = S[nf][2] * SCALE + bB.x;
            S[nf][3] = S[nf][3] * SCALE + bB.y;
            ma = fmaxf(ma, fmaxf(S[nf][0], S[nf][1]));
            mb = fmaxf(mb, fmaxf(S[nf][2], S[nf][3]));
        }
        ma = fmaxf(ma, __shfl_xor_sync(0xFFFFFFFFu, ma, 1));
        ma = fmaxf(ma, __shfl_xor_sync(0xFFFFFFFFu, ma, 2));
        mb = fmaxf(mb, __shfl_xor_sync(0xFFFFFFFFu, mb, 1));
        mb = fmaxf(mb, __shfl_xor_sync(0xFFFFFFFFu, mb, 2));

        float mna = fmaxf(m_a, ma), mnb = fmaxf(m_b, mb);
        float alA = exp2f((m_a - mna) * LOG2E);
        float alB = exp2f((m_b - mnb) * LOG2E);
        m_a = mna; m_b = mnb;

        float pa = 0.f, pb = 0.f;
#pragma unroll
        for (int nf = 0; nf < 8; ++nf) {
            int c = nf * 8 + t * 2;
            S[nf][0] = exp2f((S[nf][0] - mna) * LOG2E);
            S[nf][1] = exp2f((S[nf][1] - mna) * LOG2E);
            S[nf][2] = exp2f((S[nf][2] - mnb) * LOG2E);
            S[nf][3] = exp2f((S[nf][3] - mnb) * LOG2E);
            pa += S[nf][0] + S[nf][1];
            pb += S[nf][2] + S[nf][3];
            Ps[q0 + g][c]         = to_tf32(S[nf][0]);
            Ps[q0 + g][c + 1]     = to_tf32(S[nf][1]);
            Ps[q0 + g + 8][c]     = to_tf32(S[nf][2]);
            Ps[q0 + g + 8][c + 1] = to_tf32(S[nf][3]);
        }
        sum_a = sum_a * alA + pa;
        sum_b = sum_b * alB + pb;
#pragma unroll
        for (int df = 0; df < 8; ++df) {
            accO[df][0] *= alA; accO[df][1] *= alA;
            accO[df][2] *= alB; accO[df][3] *= alB;
        }
        __syncwarp();

        // O += P V
#pragma unroll
        for (int ks = 0; ks < 8; ++ks) {
            const int kd = ks * 8;
            float a[4] = {Ps[q0 + g][kd + t], Ps[q0 + g + 8][kd + t],
                          Ps[q0 + g][kd + t + 4], Ps[q0 + g + 8][kd + t + 4]};
#pragma unroll
            for (int df = 0; df < 8; ++df) {
                float b[2] = {to_tf32(Vs[(kd + t) * 72 + df * 8 + g]),
                              to_tf32(Vs[(kd + t + 4) * 72 + df * 8 + g])};
                mma8(accO[df], a, b);
            }
        }
        __syncthreads();
    }

    sum_a += __shfl_xor_sync(0xFFFFFFFFu, sum_a, 1);
    sum_a += __shfl_xor_sync(0xFFFFFFFFu, sum_a, 2);
    sum_b += __shfl_xor_sync(0xFFFFFFFFu, sum_b, 1);
    sum_b += __shfl_xor_sync(0xFFFFFFFFu, sum_b, 2);
    const float ia = 1.f / sum_a, ib = 1.f / sum_b;

    const int b_ = bh >> 3, h_ = bh & 7;
#pragma unroll
    for (int df = 0; df < 8; ++df) {
        int col = h_ * 64 + df * 8 + t * 2;
        if (rowA < NTOK) {
            float2 o = make_float2(accO[df][0] * ia, accO[df][1] * ia);
            *reinterpret_cast<float2*>(&g_attn[(size_t)(b_ * NTOK + rowA) * DIM + col]) = o;
        }
        if (rowB < NTOK) {
            float2 o = make_float2(accO[df][2] * ib, accO[df][3] * ib);
            *reinterpret_cast<float2*>(&g_attn[(size_t)(b_ * NTOK + rowB) * DIM + col]) = o;
        }
    }
}

// ---------------------------------------------------------------------------
extern "C" void kernel_launch(void* const* d_in, const int* in_sizes, int n_in,
                              void* d_out, int out_size) {
    (void)in_sizes; (void)n_in; (void)out_size;
    const float* x          = (const float*)d_in[0];
    const float* qkv_w      = (const float*)d_in[1];
    const float* proj_w     = (const float*)d_in[2];
    const float* proj_b     = (const float*)d_in[3];
    const float* bias_table = (const float*)d_in[4];
    const int*   rel_index  = (const int*)d_in[5];
    float* out = (float*)d_out;

    static bool attr_done = false;
    if (!attr_done) {
        cudaFuncSetAttribute(gemm_tf32<0>, cudaFuncAttributeMaxDynamicSharedMemorySize, GEMM_SMEM);
        cudaFuncSetAttribute(gemm_tf32<1>, cudaFuncAttributeMaxDynamicSharedMemorySize, GEMM_SMEM);
        cudaFuncSetAttribute(flash_attn, cudaFuncAttributeMaxDynamicSharedMemorySize, FL_SMEM);
        attr_done = true;
    }

    bias_expand<<<(NTOK * BPAD + 255) / 256, 256>>>(bias_table, rel_index);
    gemm_tf32<0><<<dim3(12, 145), 256, GEMM_SMEM>>>(x, qkv_w, nullptr, nullptr);
    flash_attn<<<dim3(5, BH), 256, FL_SMEM>>>();
    gemm_tf32<1><<<dim3(4, 145), 256, GEMM_SMEM>>>(nullptr, proj_w, proj_b, out);
}

// round 6
// speedup vs baseline: 1.0759x; 1.0759x over previous
#include <cuda_runtime.h>
#include <cuda_bf16.h>
#include <cstdint>

// ---------------------------------------------------------------------------
// Relative attention — tf32 mma GEMMs + fused flash attention.
// Round 6: fixes round-5 nullptr A-operand in proj GEMM. tf32 rounding hoisted
// out of hot loops; flash smem 88KB (bf16 bias, register Q, shuffle-P) for
// 2 blocks/SM.
// ---------------------------------------------------------------------------

namespace {
constexpr int BATCH = 32;
constexpr int NH    = 8;
constexpr int NTOK  = 577;
constexpr int DIM   = 512;
constexpr int DH    = 64;
constexpr int BH    = BATCH * NH;        // 256
constexpr int MROWS = BATCH * NTOK;      // 18464
constexpr int BPAD  = 640;               // padded bias row stride
constexpr float SCALE = 0.125f;
constexpr float LOG2E = 1.4426950408889634f;
}

// Scratch (device globals: allocation-free contract)
__device__ float g_xt[MROWS * DIM];                    // tf32-rounded x
__device__ float g_wqkv[3 * DIM * DIM];                // tf32-rounded qkv_w
__device__ float g_wproj[DIM * DIM];                   // tf32-rounded proj_w
__device__ float g_q[BH * NTOK * DH];                  // tf32-rounded
__device__ float g_k[BH * NTOK * DH];
__device__ float g_v[BH * NTOK * DH];
__device__ __nv_bfloat16 g_biasph[NH * NTOK * BPAD];   // bf16 bias, pad=-1e30
__device__ float g_attn[MROWS * DIM];                  // tf32-rounded

// ---------------------------------------------------------------------------
__device__ __forceinline__ float to_tf32(float x) {
    unsigned u;
    asm("cvt.rna.tf32.f32 %0, %1;" : "=r"(u) : "f"(x));
    return __uint_as_float(u);
}

__device__ __forceinline__ void mma8(float* d, const float* a, const float* b) {
    asm volatile(
        "mma.sync.aligned.m16n8k8.row.col.f32.tf32.tf32.f32 "
        "{%0,%1,%2,%3},{%4,%5,%6,%7},{%8,%9},{%0,%1,%2,%3};"
        : "+f"(d[0]), "+f"(d[1]), "+f"(d[2]), "+f"(d[3])
        : "r"(__float_as_uint(a[0])), "r"(__float_as_uint(a[1])),
          "r"(__float_as_uint(a[2])), "r"(__float_as_uint(a[3])),
          "r"(__float_as_uint(b[0])), "r"(__float_as_uint(b[1])));
}

__device__ __forceinline__ void cp16(void* dst, const void* src) {
    unsigned d = (unsigned)__cvta_generic_to_shared(dst);
    asm volatile("cp.async.cg.shared.global [%0], [%1], 16;\n" :: "r"(d), "l"(src));
}
__device__ __forceinline__ void cp_commit() {
    asm volatile("cp.async.commit_group;\n" ::);
}
template <int N>
__device__ __forceinline__ void cp_wait() {
    asm volatile("cp.async.wait_group %0;\n" :: "n"(N));
}

// ---------------------------------------------------------------------------
// Prep: elementwise tf32 rounding (float4 granularity).
// ---------------------------------------------------------------------------
__global__ void cvt_tf32_k(float4* __restrict__ dst, const float4* __restrict__ src, int n4) {
    int i = blockIdx.x * 256 + threadIdx.x;
    if (i >= n4) return;
    float4 v = src[i];
    dst[i] = make_float4(to_tf32(v.x), to_tf32(v.y), to_tf32(v.z), to_tf32(v.w));
}

// ---------------------------------------------------------------------------
// Bias expand: g_biasph[h][n][c] = bf16(table[rel[n][c]][h]) for c<577, else -1e30.
// ---------------------------------------------------------------------------
__global__ void bias_expand(const float* __restrict__ table,
                            const int* __restrict__ rel) {
    int idx = blockIdx.x * 256 + threadIdx.x;
    if (idx >= NTOK * BPAD) return;
    int n = idx / BPAD, c = idx - n * BPAD;
    if (c < NTOK) {
        int r = rel[n * NTOK + c];
#pragma unroll
        for (int h = 0; h < NH; ++h)
            g_biasph[((size_t)h * NTOK + n) * BPAD + c] = __float2bfloat16_rn(table[r * NH + h]);
    } else {
        __nv_bfloat16 neg = __float2bfloat16_rn(-1e30f);
#pragma unroll
        for (int h = 0; h < NH; ++h)
            g_biasph[((size_t)h * NTOK + n) * BPAD + c] = neg;
    }
}

// ---------------------------------------------------------------------------
// tf32 NT GEMM, 128x128x32 tile, cp.async double-buffered, 2 blocks/SM.
// Inputs pre-rounded to tf32: no cvt in the mainloop.
// MODE 0: scatter into g_q/g_k/g_v (rounded). MODE 1: +bias -> Cout.
// ---------------------------------------------------------------------------
namespace {
constexpr int GSTAGE = 2 * 128 * 36;                 // floats per stage (A+B)
constexpr int GEMM_SMEM = 2 * GSTAGE * 4;            // 73728 bytes
}

template <int MODE>
__global__ __launch_bounds__(256, 2) void gemm_tf32(const float* __restrict__ A,
                                                    const float* __restrict__ Bm,
                                                    const float* __restrict__ bias,
                                                    float* __restrict__ Cout) {
    extern __shared__ float smg[];
    const int tid = threadIdx.x;
    const int lane = tid & 31, wid = tid >> 5;
    const int g = lane >> 2, t = lane & 3;
    const int m0 = blockIdx.y * 128, n0 = blockIdx.x * 128;
    const int wm = (wid >> 2) * 64, wn = (wid & 3) * 32;

    float acc[4][4][4];
#pragma unroll
    for (int i = 0; i < 4; ++i)
#pragma unroll
        for (int j = 0; j < 4; ++j)
#pragma unroll
            for (int e = 0; e < 4; ++e) acc[i][j][e] = 0.f;

    auto issue = [&](int st, int k0) {
        float* As = smg + st * GSTAGE;
        float* Bs = As + 128 * 36;
#pragma unroll
        for (int it = 0; it < 4; ++it) {
            int v = tid + it * 256;
            int row = v >> 3, c4 = (v & 7) << 2;
            int gm = m0 + row; if (gm > MROWS - 1) gm = MROWS - 1;
            cp16(&As[row * 36 + c4], A + (size_t)gm * DIM + k0 + c4);
            int gn = n0 + row;    // grids exact in N: no clamp needed
            cp16(&Bs[row * 36 + c4], Bm + (size_t)gn * DIM + k0 + c4);
        }
        cp_commit();
    };

    issue(0, 0);
    for (int k0 = 0; k0 < DIM; k0 += 32) {
        const int st = (k0 >> 5) & 1;
        if (k0 + 32 < DIM) { issue(st ^ 1, k0 + 32); cp_wait<1>(); }
        else cp_wait<0>();
        __syncthreads();

        const float* As = smg + st * GSTAGE;
        const float* Bs = As + 128 * 36;
#pragma unroll
        for (int ks = 0; ks < 4; ++ks) {
            const int kd = ks * 8;
            float a[4][4];
#pragma unroll
            for (int mf = 0; mf < 4; ++mf) {
                int mr = wm + mf * 16;
                a[mf][0] = As[(mr + g) * 36 + kd + t];
                a[mf][1] = As[(mr + g + 8) * 36 + kd + t];
                a[mf][2] = As[(mr + g) * 36 + kd + t + 4];
                a[mf][3] = As[(mr + g + 8) * 36 + kd + t + 4];
            }
#pragma unroll
            for (int nf = 0; nf < 4; ++nf) {
                int nr = wn + nf * 8;
                float b[2] = {Bs[(nr + g) * 36 + kd + t],
                              Bs[(nr + g) * 36 + kd + t + 4]};
#pragma unroll
                for (int mf = 0; mf < 4; ++mf) mma8(acc[mf][nf], a[mf], b);
            }
        }
        __syncthreads();
    }

    if (MODE == 0) {
#pragma unroll
        for (int mf = 0; mf < 4; ++mf) {
#pragma unroll
            for (int ri = 0; ri < 2; ++ri) {
                int gm = m0 + wm + mf * 16 + g + ri * 8;
                if (gm >= MROWS) continue;
                int b_ = gm / NTOK;
                int n_ = gm - b_ * NTOK;
#pragma unroll
                for (int nf = 0; nf < 4; ++nf) {
#pragma unroll
                    for (int ci = 0; ci < 2; ++ci) {
                        int gn = n0 + wn + nf * 8 + t * 2 + ci;
                        int part = gn >> 9;
                        int rem = gn & 511;
                        int h_ = rem >> 6;
                        int dd = rem & 63;
                        float* dst = (part == 0) ? g_q : (part == 1) ? g_k : g_v;
                        dst[((b_ * NH + h_) * NTOK + n_) * DH + dd] =
                            to_tf32(acc[mf][nf][ri * 2 + ci]);
                    }
                }
            }
        }
    } else {
#pragma unroll
        for (int mf = 0; mf < 4; ++mf) {
#pragma unroll
            for (int ri = 0; ri < 2; ++ri) {
                int gm = m0 + wm + mf * 16 + g + ri * 8;
                if (gm >= MROWS) continue;
#pragma unroll
                for (int nf = 0; nf < 4; ++nf) {
                    int cbase = n0 + wn + nf * 8 + t * 2;
                    float2 o;
                    o.x = acc[mf][nf][ri * 2 + 0] + bias[cbase];
                    o.y = acc[mf][nf][ri * 2 + 1] + bias[cbase + 1];
                    *reinterpret_cast<float2*>(Cout + (size_t)gm * DIM + cbase) = o;
                }
            }
        }
    }
}

// ---------------------------------------------------------------------------
// Fused flash attention. 256 thr / 128 q-rows per block, 64-key tiles.
// Smem: Ks[2][64][68] fp32 + Vs[2][64][72] fp32 + Bb[128][72] bf16 = 88KB
// -> 2 blocks/SM. Q fragments in registers; P transposed by warp shuffles.
// ---------------------------------------------------------------------------
namespace {
constexpr int KS_OFF = 0;                              // floats
constexpr int VS_OFF = KS_OFF + 2 * 64 * 68;
constexpr int BB_OFF = VS_OFF + 2 * 64 * 72;           // bf16 region (as halfs)
constexpr int FL_SMEM = BB_OFF * 4 + 128 * 72 * 2;     // 90112 bytes
}

__global__ __launch_bounds__(256, 2) void flash_attn() {
    extern __shared__ float sm[];
    __nv_bfloat16* Bbh = reinterpret_cast<__nv_bfloat16*>(sm + BB_OFF);

    const int bh = blockIdx.y, qt = blockIdx.x;
    const int tid = threadIdx.x;
    const int wid = tid >> 5, lane = tid & 31;
    const int g = lane >> 2, t = lane & 3;
    const float* qb = g_q + (size_t)bh * NTOK * DH;
    const float* kb = g_k + (size_t)bh * NTOK * DH;
    const float* vb = g_v + (size_t)bh * NTOK * DH;
    const __nv_bfloat16* bp = g_biasph + (size_t)(bh & 7) * NTOK * BPAD;

    auto issueKV = [&](int st, int k0) {
        float* Ks = sm + KS_OFF + st * 64 * 68;
        float* Vs = sm + VS_OFF + st * 64 * 72;
#pragma unroll
        for (int it = 0; it < 4; ++it) {
            int v = tid + it * 256;
            int row = v >> 4, c4 = (v & 15) << 2;
            int gk = k0 + row; if (gk > NTOK - 1) gk = NTOK - 1;   // bias pad masks
            cp16(&Ks[row * 68 + c4], kb + (size_t)gk * DH + c4);
            cp16(&Vs[row * 72 + c4], vb + (size_t)gk * DH + c4);
        }
        cp_commit();
    };

    issueKV(0, 0);

    const int q0 = wid * 16;
    const int rowA = qt * 128 + q0 + g;
    const int rowB = rowA + 8;

    // Q fragments in registers (g_q is pre-rounded tf32)
    const float* qrA = qb + (size_t)min(rowA, NTOK - 1) * DH;
    const float* qrB = qb + (size_t)min(rowB, NTOK - 1) * DH;
    float qf[8][4];
#pragma unroll
    for (int ks = 0; ks < 8; ++ks) {
        qf[ks][0] = qrA[ks * 8 + t];
        qf[ks][1] = qrB[ks * 8 + t];
        qf[ks][2] = qrA[ks * 8 + t + 4];
        qf[ks][3] = qrB[ks * 8 + t + 4];
    }

    float accO[8][4];
#pragma unroll
    for (int df = 0; df < 8; ++df)
#pragma unroll
        for (int e = 0; e < 4; ++e) accO[df][e] = 0.f;
    float m_a = -1e30f, m_b = -1e30f, sum_a = 0.f, sum_b = 0.f;

    for (int kt = 0; kt < 10; ++kt) {
        const int k0 = kt * 64;
        const int st = kt & 1;
        const float* Ks = sm + KS_OFF + st * 64 * 68;
        const float* Vs = sm + VS_OFF + st * 64 * 72;

        // issue bias(kt) [bf16, 16B chunks], then KV(kt+1)
#pragma unroll
        for (int it = 0; it < 4; ++it) {
            int v = tid + it * 256;
            int row = v >> 3, c8 = (v & 7) << 3;       // half offsets
            int gq = qt * 128 + row; if (gq > NTOK - 1) gq = NTOK - 1;
            cp16(&Bbh[row * 72 + c8], bp + (size_t)gq * BPAD + k0 + c8);
        }
        cp_commit();
        if (kt < 9) issueKV(st ^ 1, k0 + 64);

        if (kt < 9) cp_wait<2>(); else cp_wait<1>();   // KV(kt) ready
        __syncthreads();

        // S = Q K^T
        float S[8][4];
#pragma unroll
        for (int nf = 0; nf < 8; ++nf)
#pragma unroll
            for (int e = 0; e < 4; ++e) S[nf][e] = 0.f;
#pragma unroll
        for (int ks = 0; ks < 8; ++ks) {
            const int kd = ks * 8;
#pragma unroll
            for (int nf = 0; nf < 8; ++nf) {
                float b[2] = {Ks[(nf * 8 + g) * 68 + kd + t],
                              Ks[(nf * 8 + g) * 68 + kd + t + 4]};
                mma8(S[nf], qf[ks], b);
            }
        }

        if (kt < 9) cp_wait<1>(); else cp_wait<0>();   // bias(kt) ready
        __syncthreads();

        // scale + bias + online softmax
        float ma = -1e30f, mb = -1e30f;
#pragma unroll
        for (int nf = 0; nf < 8; ++nf) {
            int c = nf * 8 + t * 2;
            float2 bA = __bfloat1622float2(
                *reinterpret_cast<const __nv_bfloat162*>(&Bbh[(q0 + g) * 72 + c]));
            float2 bB = __bfloat1622float2(
                *reinterpret_cast<const __nv_bfloat162*>(&Bbh[(q0 + g + 8) * 72 + c]));
            S[nf][0] = S[nf][0] * SCALE + bA.x;
            S[nf][1] = S[nf][1] * SCALE + bA.y;
            S[nf][2] = S[nf][2] * SCALE + bB.x;
            S[nf][3] = S[nf][3] * SCALE + bB.y;
            ma = fmaxf(ma, fmaxf(S[nf][0], S[nf][1]));
            mb = fmaxf(mb, fmaxf(S[nf][2], S[nf][3]));
        }
        ma = fmaxf(ma, __shfl_xor_sync(0xFFFFFFFFu, ma, 1));
        ma = fmaxf(ma, __shfl_xor_sync(0xFFFFFFFFu, ma, 2));
        mb = fmaxf(mb, __shfl_xor_sync(0xFFFFFFFFu, mb, 1));
        mb = fmaxf(mb, __shfl_xor_sync(0xFFFFFFFFu, mb, 2));

        float mna = fmaxf(m_a, ma), mnb = fmaxf(m_b, mb);
        float alA = exp2f((m_a - mna) * LOG2E);
        float alB = exp2f((m_b - mnb) * LOG2E);
        m_a = mna; m_b = mnb;

        float pa = 0.f, pb = 0.f;
#pragma unroll
        for (int nf = 0; nf < 8; ++nf) {
            S[nf][0] = to_tf32(exp2f((S[nf][0] - mna) * LOG2E));
            S[nf][1] = to_tf32(exp2f((S[nf][1] - mna) * LOG2E));
            S[nf][2] = to_tf32(exp2f((S[nf][2] - mnb) * LOG2E));
            S[nf][3] = to_tf32(exp2f((S[nf][3] - mnb) * LOG2E));
            pa += S[nf][0] + S[nf][1];
            pb += S[nf][2] + S[nf][3];
        }
        sum_a = sum_a * alA + pa;
        sum_b = sum_b * alB + pb;
#pragma unroll
        for (int df = 0; df < 8; ++df) {
            accO[df][0] *= alA; accO[df][1] *= alA;
            accO[df][2] *= alB; accO[df][3] *= alB;
        }

        // O += P V ; P a-fragments gathered by quad shuffles:
        // holder of P[row][8*ks+j] is lane (g*4 + (j>>1)), slot j&1.
        const int l0 = (lane & ~3) | (t >> 1);
        const int l1 = l0 + 2;
        const bool odd = (t & 1);
#pragma unroll
        for (int ks = 0; ks < 8; ++ks) {
            float s0A  = __shfl_sync(0xFFFFFFFFu, S[ks][0], l0);
            float s1A  = __shfl_sync(0xFFFFFFFFu, S[ks][1], l0);
            float s0B  = __shfl_sync(0xFFFFFFFFu, S[ks][2], l0);
            float s1B  = __shfl_sync(0xFFFFFFFFu, S[ks][3], l0);
            float s0A4 = __shfl_sync(0xFFFFFFFFu, S[ks][0], l1);
            float s1A4 = __shfl_sync(0xFFFFFFFFu, S[ks][1], l1);
            float s0B4 = __shfl_sync(0xFFFFFFFFu, S[ks][2], l1);
            float s1B4 = __shfl_sync(0xFFFFFFFFu, S[ks][3], l1);
            float a[4];
            a[0] = odd ? s1A : s0A;
            a[1] = odd ? s1B : s0B;
            a[2] = odd ? s1A4 : s0A4;
            a[3] = odd ? s1B4 : s0B4;
            const int kd = ks * 8;
#pragma unroll
            for (int df = 0; df < 8; ++df) {
                float b[2] = {Vs[(kd + t) * 72 + df * 8 + g],
                              Vs[(kd + t + 4) * 72 + df * 8 + g]};
                mma8(accO[df], a, b);
            }
        }
        __syncthreads();
    }

    sum_a += __shfl_xor_sync(0xFFFFFFFFu, sum_a, 1);
    sum_a += __shfl_xor_sync(0xFFFFFFFFu, sum_a, 2);
    sum_b += __shfl_xor_sync(0xFFFFFFFFu, sum_b, 1);
    sum_b += __shfl_xor_sync(0xFFFFFFFFu, sum_b, 2);
    const float ia = 1.f / sum_a, ib = 1.f / sum_b;

    const int b_ = bh >> 3, h_ = bh & 7;
#pragma unroll
    for (int df = 0; df < 8; ++df) {
        int col = h_ * 64 + df * 8 + t * 2;
        if (rowA < NTOK) {
            float2 o = make_float2(to_tf32(accO[df][0] * ia), to_tf32(accO[df][1] * ia));
            *reinterpret_cast<float2*>(&g_attn[(size_t)(b_ * NTOK + rowA) * DIM + col]) = o;
        }
        if (rowB < NTOK) {
            float2 o = make_float2(to_tf32(accO[df][2] * ib), to_tf32(accO[df][3] * ib));
            *reinterpret_cast<float2*>(&g_attn[(size_t)(b_ * NTOK + rowB) * DIM + col]) = o;
        }
    }
}

// ---------------------------------------------------------------------------
extern "C" void kernel_launch(void* const* d_in, const int* in_sizes, int n_in,
                              void* d_out, int out_size) {
    (void)in_sizes; (void)n_in; (void)out_size;
    const float* x          = (const float*)d_in[0];
    const float* qkv_w      = (const float*)d_in[1];
    const float* proj_w     = (const float*)d_in[2];
    const float* proj_b     = (const float*)d_in[3];
    const float* bias_table = (const float*)d_in[4];
    const int*   rel_index  = (const int*)d_in[5];
    float* out = (float*)d_out;

    static bool attr_done = false;
    if (!attr_done) {
        cudaFuncSetAttribute(gemm_tf32<0>, cudaFuncAttributeMaxDynamicSharedMemorySize, GEMM_SMEM);
        cudaFuncSetAttribute(gemm_tf32<1>, cudaFuncAttributeMaxDynamicSharedMemorySize, GEMM_SMEM);
        cudaFuncSetAttribute(flash_attn, cudaFuncAttributeMaxDynamicSharedMemorySize, FL_SMEM);
        attr_done = true;
    }

    float *xt = nullptr, *wq = nullptr, *wp = nullptr, *at = nullptr;
    cudaGetSymbolAddress((void**)&xt, g_xt);
    cudaGetSymbolAddress((void**)&wq, g_wqkv);
    cudaGetSymbolAddress((void**)&wp, g_wproj);
    cudaGetSymbolAddress((void**)&at, g_attn);

    // prep: tf32-round x and weights (hoists cvt out of GEMM mainloops)
    cvt_tf32_k<<<(MROWS * DIM / 4 + 255) / 256, 256>>>(
        (float4*)xt, (const float4*)x, MROWS * DIM / 4);
    cvt_tf32_k<<<(3 * DIM * DIM / 4 + 255) / 256, 256>>>(
        (float4*)wq, (const float4*)qkv_w, 3 * DIM * DIM / 4);
    cvt_tf32_k<<<(DIM * DIM / 4 + 255) / 256, 256>>>(
        (float4*)wp, (const float4*)proj_w, DIM * DIM / 4);
    bias_expand<<<(NTOK * BPAD + 255) / 256, 256>>>(bias_table, rel_index);

    gemm_tf32<0><<<dim3(12, 145), 256, GEMM_SMEM>>>(xt, wq, nullptr, nullptr);
    flash_attn<<<dim3(5, BH), 256, FL_SMEM>>>();
    gemm_tf32<1><<<dim3(4, 145), 256, GEMM_SMEM>>>(at, wp, proj_b, out);
}

// round 8
// speedup vs baseline: 1.1727x; 1.0900x over previous
#include <cuda_runtime.h>
#include <cuda_bf16.h>
#include <cstdint>

// ---------------------------------------------------------------------------
// Relative attention — tf32 mma.sync with ldmatrix fragment loads.
// Round 8: sm_100 target has no tcgen05 (ptxas rejects) — optimize the legacy
// path instead: ldmatrix.x4.b16 fragment loads in GEMM + flash (V stored
// transposed so PV fragments also come from ldmatrix).
// ---------------------------------------------------------------------------

namespace {
constexpr int BATCH = 32;
constexpr int NH    = 8;
constexpr int NTOK  = 577;
constexpr int DIM   = 512;
constexpr int DH    = 64;
constexpr int BH    = BATCH * NH;        // 256
constexpr int MROWS = BATCH * NTOK;      // 18464
constexpr int BPAD  = 640;               // padded bias row stride
constexpr int VP    = 640;               // padded V^T row stride (tokens)
constexpr float SCALE = 0.125f;
constexpr float LOG2E = 1.4426950408889634f;
}

// Scratch (device globals: allocation-free contract)
__device__ float g_xt[MROWS * DIM];                    // tf32-rounded x
__device__ float g_wqkv[3 * DIM * DIM];                // tf32-rounded qkv_w
__device__ float g_wproj[DIM * DIM];                   // tf32-rounded proj_w
__device__ float g_q[BH * NTOK * DH];                  // tf32-rounded
__device__ float g_k[BH * NTOK * DH];
__device__ float g_vt[BH * DH * VP];                   // V^T [bh][d][tok], pad 0
__device__ __nv_bfloat16 g_biasph[NH * NTOK * BPAD];   // bf16 bias, pad=-1e30
__device__ float g_attn[MROWS * DIM];                  // tf32-rounded

// ---------------------------------------------------------------------------
__device__ __forceinline__ float to_tf32(float x) {
    unsigned u;
    asm("cvt.rna.tf32.f32 %0, %1;" : "=r"(u) : "f"(x));
    return __uint_as_float(u);
}

__device__ __forceinline__ void mma8(float* d, const float* a, const float* b) {
    asm volatile(
        "mma.sync.aligned.m16n8k8.row.col.f32.tf32.tf32.f32 "
        "{%0,%1,%2,%3},{%4,%5,%6,%7},{%8,%9},{%0,%1,%2,%3};"
        : "+f"(d[0]), "+f"(d[1]), "+f"(d[2]), "+f"(d[3])
        : "r"(__float_as_uint(a[0])), "r"(__float_as_uint(a[1])),
          "r"(__float_as_uint(a[2])), "r"(__float_as_uint(a[3])),
          "r"(__float_as_uint(b[0])), "r"(__float_as_uint(b[1])));
}

__device__ __forceinline__ void mma8u(float* d, const uint32_t* a, const uint32_t* b) {
    asm volatile(
        "mma.sync.aligned.m16n8k8.row.col.f32.tf32.tf32.f32 "
        "{%0,%1,%2,%3},{%4,%5,%6,%7},{%8,%9},{%0,%1,%2,%3};"
        : "+f"(d[0]), "+f"(d[1]), "+f"(d[2]), "+f"(d[3])
        : "r"(a[0]), "r"(a[1]), "r"(a[2]), "r"(a[3]),
          "r"(b[0]), "r"(b[1]));
}

__device__ __forceinline__ void mma8fu(float* d, const float* a, const uint32_t* b) {
    asm volatile(
        "mma.sync.aligned.m16n8k8.row.col.f32.tf32.tf32.f32 "
        "{%0,%1,%2,%3},{%4,%5,%6,%7},{%8,%9},{%0,%1,%2,%3};"
        : "+f"(d[0]), "+f"(d[1]), "+f"(d[2]), "+f"(d[3])
        : "r"(__float_as_uint(a[0])), "r"(__float_as_uint(a[1])),
          "r"(__float_as_uint(a[2])), "r"(__float_as_uint(a[3])),
          "r"(b[0]), "r"(b[1]));
}

__device__ __forceinline__ void ldsm4(uint32_t* r, uint32_t addr) {
    asm volatile("ldmatrix.sync.aligned.m8n8.x4.shared.b16 {%0,%1,%2,%3}, [%4];"
                 : "=r"(r[0]), "=r"(r[1]), "=r"(r[2]), "=r"(r[3]) : "r"(addr));
}

__device__ __forceinline__ void cp16(void* dst, const void* src) {
    unsigned d = (unsigned)__cvta_generic_to_shared(dst);
    asm volatile("cp.async.cg.shared.global [%0], [%1], 16;\n" :: "r"(d), "l"(src));
}
__device__ __forceinline__ void cp_commit() {
    asm volatile("cp.async.commit_group;\n" ::);
}
template <int N>
__device__ __forceinline__ void cp_wait() {
    asm volatile("cp.async.wait_group %0;\n" :: "n"(N));
}

// ---------------------------------------------------------------------------
// Prep kernels
// ---------------------------------------------------------------------------
__global__ void cvt_tf32_k(float4* __restrict__ dst, const float4* __restrict__ src, int n4) {
    int i = blockIdx.x * 256 + threadIdx.x;
    if (i >= n4) return;
    float4 v = src[i];
    dst[i] = make_float4(to_tf32(v.x), to_tf32(v.y), to_tf32(v.z), to_tf32(v.w));
}

__global__ void bias_expand(const float* __restrict__ table,
                            const int* __restrict__ rel) {
    int idx = blockIdx.x * 256 + threadIdx.x;
    if (idx >= NTOK * BPAD) return;
    int n = idx / BPAD, c = idx - n * BPAD;
    if (c < NTOK) {
        int r = rel[n * NTOK + c];
#pragma unroll
        for (int h = 0; h < NH; ++h)
            g_biasph[((size_t)h * NTOK + n) * BPAD + c] = __float2bfloat16_rn(table[r * NH + h]);
    } else {
        __nv_bfloat16 neg = __float2bfloat16_rn(-1e30f);
#pragma unroll
        for (int h = 0; h < NH; ++h)
            g_biasph[((size_t)h * NTOK + n) * BPAD + c] = neg;
    }
}

// ---------------------------------------------------------------------------
// tf32 NT GEMM, 128x128x32 tile, cp.async double-buffered, 2 blocks/SM,
// ldmatrix fragment loads (stride-36 rows are conflict-free in 8-row phases).
// MODE 0: scatter into g_q/g_k/g_vt (rounded). MODE 1: +bias -> Cout.
// ---------------------------------------------------------------------------
namespace {
constexpr int GSTAGE = 2 * 128 * 36;                 // floats per stage (A+B)
constexpr int GEMM_SMEM = 2 * GSTAGE * 4;            // 73728 bytes
}

template <int MODE>
__global__ __launch_bounds__(256, 2) void gemm_tf32(const float* __restrict__ A,
                                                    const float* __restrict__ Bm,
                                                    const float* __restrict__ bias,
                                                    float* __restrict__ Cout) {
    extern __shared__ float smg[];
    const int tid = threadIdx.x;
    const int lane = tid & 31, wid = tid >> 5;
    const int g = lane >> 2, t = lane & 3;
    const int m0 = blockIdx.y * 128, n0 = blockIdx.x * 128;
    const int wm = (wid >> 2) * 64, wn = (wid & 3) * 32;
    const uint32_t sb = (uint32_t)__cvta_generic_to_shared(smg);

    // per-lane ldmatrix offsets (floats)
    const int laneA = (((lane >> 3) & 1) * 8 + (lane & 7)) * 36 + (lane >> 4) * 4;
    const int laneB = ((lane >> 4) * 8 + (lane & 7)) * 36 + ((lane >> 3) & 1) * 4;

    float acc[4][4][4];
#pragma unroll
    for (int i = 0; i < 4; ++i)
#pragma unroll
        for (int j = 0; j < 4; ++j)
#pragma unroll
            for (int e = 0; e < 4; ++e) acc[i][j][e] = 0.f;

    auto issue = [&](int st, int k0) {
        float* As = smg + st * GSTAGE;
        float* Bs = As + 128 * 36;
#pragma unroll
        for (int it = 0; it < 4; ++it) {
            int v = tid + it * 256;
            int row = v >> 3, c4 = (v & 7) << 2;
            int gm = m0 + row; if (gm > MROWS - 1) gm = MROWS - 1;
            cp16(&As[row * 36 + c4], A + (size_t)gm * DIM + k0 + c4);
            int gn = n0 + row;    // grids exact in N: no clamp needed
            cp16(&Bs[row * 36 + c4], Bm + (size_t)gn * DIM + k0 + c4);
        }
        cp_commit();
    };

    issue(0, 0);
    for (int k0 = 0; k0 < DIM; k0 += 32) {
        const int st = (k0 >> 5) & 1;
        if (k0 + 32 < DIM) { issue(st ^ 1, k0 + 32); cp_wait<1>(); }
        else cp_wait<0>();
        __syncthreads();

        const uint32_t aAddr = sb + (uint32_t)(st * GSTAGE + wm * 36 + laneA) * 4;
        const uint32_t bAddr = sb + (uint32_t)(st * GSTAGE + 128 * 36 + wn * 36 + laneB) * 4;
#pragma unroll
        for (int ks = 0; ks < 4; ++ks) {
            const int kd4 = ks * 8 * 4;           // bytes
            uint32_t aR[4][4];
#pragma unroll
            for (int mf = 0; mf < 4; ++mf)
                ldsm4(aR[mf], aAddr + mf * (16 * 36 * 4) + kd4);
            uint32_t bR[2][4];
#pragma unroll
            for (int p = 0; p < 2; ++p)
                ldsm4(bR[p], bAddr + p * (16 * 36 * 4) + kd4);
#pragma unroll
            for (int p = 0; p < 2; ++p)
#pragma unroll
                for (int s = 0; s < 2; ++s) {
                    const int nf = p * 2 + s;
#pragma unroll
                    for (int mf = 0; mf < 4; ++mf)
                        mma8u(acc[mf][nf], aR[mf], &bR[p][2 * s]);
                }
        }
        __syncthreads();
    }

    if (MODE == 0) {
#pragma unroll
        for (int mf = 0; mf < 4; ++mf) {
#pragma unroll
            for (int ri = 0; ri < 2; ++ri) {
                int gm = m0 + wm + mf * 16 + g + ri * 8;
                if (gm >= MROWS) continue;
                int b_ = gm / NTOK;
                int n_ = gm - b_ * NTOK;
#pragma unroll
                for (int nf = 0; nf < 4; ++nf) {
#pragma unroll
                    for (int ci = 0; ci < 2; ++ci) {
                        int gn = n0 + wn + nf * 8 + t * 2 + ci;
                        int part = gn >> 9;
                        int rem = gn & 511;
                        int h_ = rem >> 6;
                        int dd = rem & 63;
                        float val = to_tf32(acc[mf][nf][ri * 2 + ci]);
                        int bh_ = b_ * NH + h_;
                        if (part == 0)      g_q[((size_t)bh_ * NTOK + n_) * DH + dd] = val;
                        else if (part == 1) g_k[((size_t)bh_ * NTOK + n_) * DH + dd] = val;
                        else                g_vt[((size_t)bh_ * DH + dd) * VP + n_] = val;
                    }
                }
            }
        }
    } else {
#pragma unroll
        for (int mf = 0; mf < 4; ++mf) {
#pragma unroll
            for (int ri = 0; ri < 2; ++ri) {
                int gm = m0 + wm + mf * 16 + g + ri * 8;
                if (gm >= MROWS) continue;
#pragma unroll
                for (int nf = 0; nf < 4; ++nf) {
                    int cbase = n0 + wn + nf * 8 + t * 2;
                    float2 o;
                    o.x = acc[mf][nf][ri * 2 + 0] + bias[cbase];
                    o.y = acc[mf][nf][ri * 2 + 1] + bias[cbase + 1];
                    *reinterpret_cast<float2*>(Cout + (size_t)gm * DIM + cbase) = o;
                }
            }
        }
    }
}

// ---------------------------------------------------------------------------
// Fused flash attention. 256 thr / 128 q-rows, 64-key tiles, 2 blocks/SM.
// K and V^T fragments via ldmatrix; Q in registers; bf16 bias; shuffle-P.
// Smem: Ks[2][64][68] + Vt[2][64][68] fp32 + Bb[128][72] bf16 = 88064 B.
// ---------------------------------------------------------------------------
namespace {
constexpr int KS_OFF = 0;                              // floats
constexpr int VS_OFF = KS_OFF + 2 * 64 * 68;
constexpr int BB_OFF = VS_OFF + 2 * 64 * 68;           // bf16 region
constexpr int FL_SMEM = BB_OFF * 4 + 128 * 72 * 2;     // 88064 bytes
}

__global__ __launch_bounds__(256, 2) void flash_attn() {
    extern __shared__ float sm[];
    __nv_bfloat16* Bbh = reinterpret_cast<__nv_bfloat16*>(sm + BB_OFF);
    const uint32_t sb = (uint32_t)__cvta_generic_to_shared(sm);

    const int bh = blockIdx.y, qt = blockIdx.x;
    const int tid = threadIdx.x;
    const int wid = tid >> 5, lane = tid & 31;
    const int g = lane >> 2, t = lane & 3;
    const float* qb = g_q + (size_t)bh * NTOK * DH;
    const float* kb = g_k + (size_t)bh * NTOK * DH;
    const float* vtb = g_vt + (size_t)bh * DH * VP;
    const __nv_bfloat16* bp = g_biasph + (size_t)(bh & 7) * NTOK * BPAD;

    // ldmatrix per-lane offset for B-fragments (stride-68 rows)
    const int laneB68 = ((lane >> 4) * 8 + (lane & 7)) * 68 + ((lane >> 3) & 1) * 4;

    auto issueKV = [&](int st, int k0) {
        float* Ks = sm + KS_OFF + st * 64 * 68;
        float* Vt = sm + VS_OFF + st * 64 * 68;
#pragma unroll
        for (int it = 0; it < 4; ++it) {
            int v = tid + it * 256;
            int row = v >> 4, c4 = (v & 15) << 2;
            int gk = k0 + row; if (gk > NTOK - 1) gk = NTOK - 1;   // bias pad masks
            cp16(&Ks[row * 68 + c4], kb + (size_t)gk * DH + c4);
            // V^T tile: row = d, cols = keys (VP=640 pad keeps reads in-bounds)
            cp16(&Vt[row * 68 + c4], vtb + (size_t)row * VP + k0 + c4);
        }
        cp_commit();
    };

    issueKV(0, 0);

    const int q0 = wid * 16;
    const int rowA = qt * 128 + q0 + g;
    const int rowB = rowA + 8;

    const float* qrA = qb + (size_t)min(rowA, NTOK - 1) * DH;
    const float* qrB = qb + (size_t)min(rowB, NTOK - 1) * DH;
    float qf[8][4];
#pragma unroll
    for (int ks = 0; ks < 8; ++ks) {
        qf[ks][0] = qrA[ks * 8 + t];
        qf[ks][1] = qrB[ks * 8 + t];
        qf[ks][2] = qrA[ks * 8 + t + 4];
        qf[ks][3] = qrB[ks * 8 + t + 4];
    }

    float accO[8][4];
#pragma unroll
    for (int df = 0; df < 8; ++df)
#pragma unroll
        for (int e = 0; e < 4; ++e) accO[df][e] = 0.f;
    float m_a = -1e30f, m_b = -1e30f, sum_a = 0.f, sum_b = 0.f;

    for (int kt = 0; kt < 10; ++kt) {
        const int k0 = kt * 64;
        const int st = kt & 1;
        const uint32_t ksAddr = sb + (uint32_t)(KS_OFF + st * 64 * 68 + laneB68) * 4;
        const uint32_t vtAddr = sb + (uint32_t)(VS_OFF + st * 64 * 68 + laneB68) * 4;

#pragma unroll
        for (int it = 0; it < 4; ++it) {
            int v = tid + it * 256;
            int row = v >> 3, c8 = (v & 7) << 3;
            int gq = qt * 128 + row; if (gq > NTOK - 1) gq = NTOK - 1;
            cp16(&Bbh[row * 72 + c8], bp + (size_t)gq * BPAD + k0 + c8);
        }
        cp_commit();
        if (kt < 9) issueKV(st ^ 1, k0 + 64);

        if (kt < 9) cp_wait<2>(); else cp_wait<1>();
        __syncthreads();

        // S = Q K^T (B-fragments via ldmatrix)
        float S[8][4];
#pragma unroll
        for (int nf = 0; nf < 8; ++nf)
#pragma unroll
            for (int e = 0; e < 4; ++e) S[nf][e] = 0.f;
#pragma unroll
        for (int ks = 0; ks < 8; ++ks) {
            const int kd4 = ks * 8 * 4;
#pragma unroll
            for (int p = 0; p < 4; ++p) {
                uint32_t bR[4];
                ldsm4(bR, ksAddr + p * (16 * 68 * 4) + kd4);
                mma8fu(S[p * 2 + 0], qf[ks], &bR[0]);
                mma8fu(S[p * 2 + 1], qf[ks], &bR[2]);
            }
        }

        if (kt < 9) cp_wait<1>(); else cp_wait<0>();
        __syncthreads();

        // scale + bias + online softmax
        float ma = -1e30f, mb = -1e30f;
#pragma unroll
        for (int nf = 0; nf < 8; ++nf) {
            int c = nf * 8 + t * 2;
            float2 bA = __bfloat1622float2(
                *reinterpret_cast<const __nv_bfloat162*>(&Bbh[(q0 + g) * 72 + c]));
            float2 bB = __bfloat1622float2(
                *reinterpret_cast<const __nv_bfloat162*>(&Bbh[(q0 + g + 8) * 72 + c]));
            S[nf][0] = S[nf][0] * SCALE + bA.x;
            S[nf][1] = S[nf][1] * SCALE + bA.y;
            S[nf][2] = S[nf][2] * SCALE + bB.x;
            S[nf][3] = S[nf][3] * SCALE + bB.y;
            ma = fmaxf(ma, fmaxf(S[nf][0], S[nf][1]));
            mb = fmaxf(mb, fmaxf(S[nf][2], S[nf][3]));
        }
        ma = fmaxf(ma, __shfl_xor_sync(0xFFFFFFFFu, ma, 1));
        ma = fmaxf(ma, __shfl_xor_sync(0xFFFFFFFFu, ma, 2));
        mb = fmaxf(mb, __shfl_xor_sync(0xFFFFFFFFu, mb, 1));
        mb = fmaxf(mb, __shfl_xor_sync(0xFFFFFFFFu, mb, 2));

        float mna = fmaxf(m_a, ma), mnb = fmaxf(m_b, mb);
        float alA = exp2f((m_a - mna) * LOG2E);
        float alB = exp2f((m_b - mnb) * LOG2E);
        m_a = mna; m_b = mnb;

        float pa = 0.f, pb = 0.f;
#pragma unroll
        for (int nf = 0; nf < 8; ++nf) {
            S[nf][0] = to_tf32(exp2f((S[nf][0] - mna) * LOG2E));
            S[nf][1] = to_tf32(exp2f((S[nf][1] - mna) * LOG2E));
            S[nf][2] = to_tf32(exp2f((S[nf][2] - mnb) * LOG2E));
            S[nf][3] = to_tf32(exp2f((S[nf][3] - mnb) * LOG2E));
            pa += S[nf][0] + S[nf][1];
            pb += S[nf][2] + S[nf][3];
        }
        sum_a = sum_a * alA + pa;
        sum_b = sum_b * alB + pb;
#pragma unroll
        for (int df = 0; df < 8; ++df) {
            accO[df][0] *= alA; accO[df][1] *= alA;
            accO[df][2] *= alB; accO[df][3] *= alB;
        }

        // O += P V ; P a-fragments via quad shuffles, V^T b-fragments via ldmatrix
        const int l0 = (lane & ~3) | (t >> 1);
        const int l1 = l0 + 2;
        const bool odd = (t & 1);
#pragma unroll
        for (int ks = 0; ks < 8; ++ks) {
            float s0A  = __shfl_sync(0xFFFFFFFFu, S[ks][0], l0);
            float s1A  = __shfl_sync(0xFFFFFFFFu, S[ks][1], l0);
            float s0B  = __shfl_sync(0xFFFFFFFFu, S[ks][2], l0);
            float s1B  = __shfl_sync(0xFFFFFFFFu, S[ks][3], l0);
            float s0A4 = __shfl_sync(0xFFFFFFFFu, S[ks][0], l1);
            float s1A4 = __shfl_sync(0xFFFFFFFFu, S[ks][1], l1);
            float s0B4 = __shfl_sync(0xFFFFFFFFu, S[ks][2], l1);
            float s1B4 = __shfl_sync(0xFFFFFFFFu, S[ks][3], l1);
            float a[4];
            a[0] = odd ? s1A : s0A;
            a[1] = odd ? s1B : s0B;
            a[2] = odd ? s1A4 : s0A4;
            a[3] = odd ? s1B4 : s0B4;
            const int kd4 = ks * 8 * 4;
#pragma unroll
            for (int p = 0; p < 4; ++p) {
                uint32_t bR[4];
                ldsm4(bR, vtAddr + p * (16 * 68 * 4) + kd4);
                mma8fu(accO[p * 2 + 0], a, &bR[0]);
                mma8fu(accO[p * 2 + 1], a, &bR[2]);
            }
        }
        __syncthreads();
    }

    sum_a += __shfl_xor_sync(0xFFFFFFFFu, sum_a, 1);
    sum_a += __shfl_xor_sync(0xFFFFFFFFu, sum_a, 2);
    sum_b += __shfl_xor_sync(0xFFFFFFFFu, sum_b, 1);
    sum_b += __shfl_xor_sync(0xFFFFFFFFu, sum_b, 2);
    const float ia = 1.f / sum_a, ib = 1.f / sum_b;

    const int b_ = bh >> 3, h_ = bh & 7;
#pragma unroll
    for (int df = 0; df < 8; ++df) {
        int col = h_ * 64 + df * 8 + t * 2;
        if (rowA < NTOK) {
            float2 o = make_float2(to_tf32(accO[df][0] * ia), to_tf32(accO[df][1] * ia));
            *reinterpret_cast<float2*>(&g_attn[(size_t)(b_ * NTOK + rowA) * DIM + col]) = o;
        }
        if (rowB < NTOK) {
            float2 o = make_float2(to_tf32(accO[df][2] * ib), to_tf32(accO[df][3] * ib));
            *reinterpret_cast<float2*>(&g_attn[(size_t)(b_ * NTOK + rowB) * DIM + col]) = o;
        }
    }
}

// ---------------------------------------------------------------------------
extern "C" void kernel_launch(void* const* d_in, const int* in_sizes, int n_in,
                              void* d_out, int out_size) {
    (void)in_sizes; (void)n_in; (void)out_size;
    const float* x          = (const float*)d_in[0];
    const float* qkv_w      = (const float*)d_in[1];
    const float* proj_w     = (const float*)d_in[2];
    const float* proj_b     = (const float*)d_in[3];
    const float* bias_table = (const float*)d_in[4];
    const int*   rel_index  = (const int*)d_in[5];
    float* out = (float*)d_out;

    static bool attr_done = false;
    if (!attr_done) {
        cudaFuncSetAttribute(gemm_tf32<0>, cudaFuncAttributeMaxDynamicSharedMemorySize, GEMM_SMEM);
        cudaFuncSetAttribute(gemm_tf32<1>, cudaFuncAttributeMaxDynamicSharedMemorySize, GEMM_SMEM);
        cudaFuncSetAttribute(flash_attn, cudaFuncAttributeMaxDynamicSharedMemorySize, FL_SMEM);
        attr_done = true;
    }

    float *xt = nullptr, *wq = nullptr, *wp = nullptr, *at = nullptr;
    cudaGetSymbolAddress((void**)&xt, g_xt);
    cudaGetSymbolAddress((void**)&wq, g_wqkv);
    cudaGetSymbolAddress((void**)&wp, g_wproj);
    cudaGetSymbolAddress((void**)&at, g_attn);

    // prep: tf32-round x and weights (hoists cvt out of GEMM mainloops)
    cvt_tf32_k<<<(MROWS * DIM / 4 + 255) / 256, 256>>>(
        (float4*)xt, (const float4*)x, MROWS * DIM / 4);
    cvt_tf32_k<<<(3 * DIM * DIM / 4 + 255) / 256, 256>>>(
        (float4*)wq, (const float4*)qkv_w, 3 * DIM * DIM / 4);
    cvt_tf32_k<<<(DIM * DIM / 4 + 255) / 256, 256>>>(
        (float4*)wp, (const float4*)proj_w, DIM * DIM / 4);
    bias_expand<<<(NTOK * BPAD + 255) / 256, 256>>>(bias_table, rel_index);

    gemm_tf32<0><<<dim3(12, 145), 256, GEMM_SMEM>>>(xt, wq, nullptr, nullptr);
    flash_attn<<<dim3(5, BH), 256, FL_SMEM>>>();
    gemm_tf32<1><<<dim3(4, 145), 256, GEMM_SMEM>>>(at, wp, proj_b, out);
}

// round 9
// speedup vs baseline: 1.1729x; 1.0002x over previous
#include <cuda_runtime.h>
#include <cuda_bf16.h>
#include <cstdint>

// ---------------------------------------------------------------------------
// Relative attention — tf32 mma.sync with ldmatrix fragment loads.
// Round 8: sm_100 target has no tcgen05 (ptxas rejects) — optimize the legacy
// path instead: ldmatrix.x4.b16 fragment loads in GEMM + flash (V stored
// transposed so PV fragments also come from ldmatrix).
// ---------------------------------------------------------------------------

namespace {
constexpr int BATCH = 32;
constexpr int NH    = 8;
constexpr int NTOK  = 577;
constexpr int DIM   = 512;
constexpr int DH    = 64;
constexpr int BH    = BATCH * NH;        // 256
constexpr int MROWS = BATCH * NTOK;      // 18464
constexpr int BPAD  = 640;               // padded bias row stride
constexpr int VP    = 640;               // padded V^T row stride (tokens)
constexpr float SCALE = 0.125f;
constexpr float LOG2E = 1.4426950408889634f;
}

// Scratch (device globals: allocation-free contract)
__device__ float g_xt[MROWS * DIM];                    // tf32-rounded x
__device__ float g_wqkv[3 * DIM * DIM];                // tf32-rounded qkv_w
__device__ float g_wproj[DIM * DIM];                   // tf32-rounded proj_w
__device__ float g_q[BH * NTOK * DH];                  // tf32-rounded
__device__ float g_k[BH * NTOK * DH];
__device__ float g_vt[BH * DH * VP];                   // V^T [bh][d][tok], pad 0
__device__ __nv_bfloat16 g_biasph[NH * NTOK * BPAD];   // bf16 bias, pad=-1e30
__device__ float g_attn[MROWS * DIM];                  // tf32-rounded

// ---------------------------------------------------------------------------
__device__ __forceinline__ float to_tf32(float x) {
    unsigned u;
    asm("cvt.rna.tf32.f32 %0, %1;" : "=r"(u) : "f"(x));
    return __uint_as_float(u);
}

__device__ __forceinline__ void mma8(float* d, const float* a, const float* b) {
    asm volatile(
        "mma.sync.aligned.m16n8k8.row.col.f32.tf32.tf32.f32 "
        "{%0,%1,%2,%3},{%4,%5,%6,%7},{%8,%9},{%0,%1,%2,%3};"
        : "+f"(d[0]), "+f"(d[1]), "+f"(d[2]), "+f"(d[3])
        : "r"(__float_as_uint(a[0])), "r"(__float_as_uint(a[1])),
          "r"(__float_as_uint(a[2])), "r"(__float_as_uint(a[3])),
          "r"(__float_as_uint(b[0])), "r"(__float_as_uint(b[1])));
}

__device__ __forceinline__ void mma8u(float* d, const uint32_t* a, const uint32_t* b) {
    asm volatile(
        "mma.sync.aligned.m16n8k8.row.col.f32.tf32.tf32.f32 "
        "{%0,%1,%2,%3},{%4,%5,%6,%7},{%8,%9},{%0,%1,%2,%3};"
        : "+f"(d[0]), "+f"(d[1]), "+f"(d[2]), "+f"(d[3])
        : "r"(a[0]), "r"(a[1]), "r"(a[2]), "r"(a[3]),
          "r"(b[0]), "r"(b[1]));
}

__device__ __forceinline__ void mma8fu(float* d, const float* a, const uint32_t* b) {
    asm volatile(
        "mma.sync.aligned.m16n8k8.row.col.f32.tf32.tf32.f32 "
        "{%0,%1,%2,%3},{%4,%5,%6,%7},{%8,%9},{%0,%1,%2,%3};"
        : "+f"(d[0]), "+f"(d[1]), "+f"(d[2]), "+f"(d[3])
        : "r"(__float_as_uint(a[0])), "r"(__float_as_uint(a[1])),
          "r"(__float_as_uint(a[2])), "r"(__float_as_uint(a[3])),
          "r"(b[0]), "r"(b[1]));
}

__device__ __forceinline__ void ldsm4(uint32_t* r, uint32_t addr) {
    asm volatile("ldmatrix.sync.aligned.m8n8.x4.shared.b16 {%0,%1,%2,%3}, [%4];"
                 : "=r"(r[0]), "=r"(r[1]), "=r"(r[2]), "=r"(r[3]) : "r"(addr));
}

__device__ __forceinline__ void cp16(void* dst, const void* src) {
    unsigned d = (unsigned)__cvta_generic_to_shared(dst);
    asm volatile("cp.async.cg.shared.global [%0], [%1], 16;\n" :: "r"(d), "l"(src));
}
__device__ __forceinline__ void cp_commit() {
    asm volatile("cp.async.commit_group;\n" ::);
}
template <int N>
__device__ __forceinline__ void cp_wait() {
    asm volatile("cp.async.wait_group %0;\n" :: "n"(N));
}

// ---------------------------------------------------------------------------
// Prep kernels
// ---------------------------------------------------------------------------
__global__ void cvt_tf32_k(float4* __restrict__ dst, const float4* __restrict__ src, int n4) {
    int i = blockIdx.x * 256 + threadIdx.x;
    if (i >= n4) return;
    float4 v = src[i];
    dst[i] = make_float4(to_tf32(v.x), to_tf32(v.y), to_tf32(v.z), to_tf32(v.w));
}

__global__ void bias_expand(const float* __restrict__ table,
                            const int* __restrict__ rel) {
    int idx = blockIdx.x * 256 + threadIdx.x;
    if (idx >= NTOK * BPAD) return;
    int n = idx / BPAD, c = idx - n * BPAD;
    if (c < NTOK) {
        int r = rel[n * NTOK + c];
#pragma unroll
        for (int h = 0; h < NH; ++h)
            g_biasph[((size_t)h * NTOK + n) * BPAD + c] = __float2bfloat16_rn(table[r * NH + h]);
    } else {
        __nv_bfloat16 neg = __float2bfloat16_rn(-1e30f);
#pragma unroll
        for (int h = 0; h < NH; ++h)
            g_biasph[((size_t)h * NTOK + n) * BPAD + c] = neg;
    }
}

// ---------------------------------------------------------------------------
// tf32 NT GEMM, 128x128x32 tile, cp.async double-buffered, 2 blocks/SM,
// ldmatrix fragment loads (stride-36 rows are conflict-free in 8-row phases).
// MODE 0: scatter into g_q/g_k/g_vt (rounded). MODE 1: +bias -> Cout.
// ---------------------------------------------------------------------------
namespace {
constexpr int GSTAGE = 2 * 128 * 36;                 // floats per stage (A+B)
constexpr int GEMM_SMEM = 2 * GSTAGE * 4;            // 73728 bytes
}

template <int MODE>
__global__ __launch_bounds__(256, 2) void gemm_tf32(const float* __restrict__ A,
                                                    const float* __restrict__ Bm,
                                                    const float* __restrict__ bias,
                                                    float* __restrict__ Cout) {
    extern __shared__ float smg[];
    const int tid = threadIdx.x;
    const int lane = tid & 31, wid = tid >> 5;
    const int g = lane >> 2, t = lane & 3;
    const int m0 = blockIdx.y * 128, n0 = blockIdx.x * 128;
    const int wm = (wid >> 2) * 64, wn = (wid & 3) * 32;
    const uint32_t sb = (uint32_t)__cvta_generic_to_shared(smg);

    // per-lane ldmatrix offsets (floats)
    const int laneA = (((lane >> 3) & 1) * 8 + (lane & 7)) * 36 + (lane >> 4) * 4;
    const int laneB = ((lane >> 4) * 8 + (lane & 7)) * 36 + ((lane >> 3) & 1) * 4;

    float acc[4][4][4];
#pragma unroll
    for (int i = 0; i < 4; ++i)
#pragma unroll
        for (int j = 0; j < 4; ++j)
#pragma unroll
            for (int e = 0; e < 4; ++e) acc[i][j][e] = 0.f;

    auto issue = [&](int st, int k0) {
        float* As = smg + st * GSTAGE;
        float* Bs = As + 128 * 36;
#pragma unroll
        for (int it = 0; it < 4; ++it) {
            int v = tid + it * 256;
            int row = v >> 3, c4 = (v & 7) << 2;
            int gm = m0 + row; if (gm > MROWS - 1) gm = MROWS - 1;
            cp16(&As[row * 36 + c4], A + (size_t)gm * DIM + k0 + c4);
            int gn = n0 + row;    // grids exact in N: no clamp needed
            cp16(&Bs[row * 36 + c4], Bm + (size_t)gn * DIM + k0 + c4);
        }
        cp_commit();
    };

    issue(0, 0);
    for (int k0 = 0; k0 < DIM; k0 += 32) {
        const int st = (k0 >> 5) & 1;
        if (k0 + 32 < DIM) { issue(st ^ 1, k0 + 32); cp_wait<1>(); }
        else cp_wait<0>();
        __syncthreads();

        const uint32_t aAddr = sb + (uint32_t)(st * GSTAGE + wm * 36 + laneA) * 4;
        const uint32_t bAddr = sb + (uint32_t)(st * GSTAGE + 128 * 36 + wn * 36 + laneB) * 4;
#pragma unroll
        for (int ks = 0; ks < 4; ++ks) {
            const int kd4 = ks * 8 * 4;           // bytes
            uint32_t aR[4][4];
#pragma unroll
            for (int mf = 0; mf < 4; ++mf)
                ldsm4(aR[mf], aAddr + mf * (16 * 36 * 4) + kd4);
            uint32_t bR[2][4];
#pragma unroll
            for (int p = 0; p < 2; ++p)
                ldsm4(bR[p], bAddr + p * (16 * 36 * 4) + kd4);
#pragma unroll
            for (int p = 0; p < 2; ++p)
#pragma unroll
                for (int s = 0; s < 2; ++s) {
                    const int nf = p * 2 + s;
#pragma unroll
                    for (int mf = 0; mf < 4; ++mf)
                        mma8u(acc[mf][nf], aR[mf], &bR[p][2 * s]);
                }
        }
        __syncthreads();
    }

    if (MODE == 0) {
#pragma unroll
        for (int mf = 0; mf < 4; ++mf) {
#pragma unroll
            for (int ri = 0; ri < 2; ++ri) {
                int gm = m0 + wm + mf * 16 + g + ri * 8;
                if (gm >= MROWS) continue;
                int b_ = gm / NTOK;
                int n_ = gm - b_ * NTOK;
#pragma unroll
                for (int nf = 0; nf < 4; ++nf) {
#pragma unroll
                    for (int ci = 0; ci < 2; ++ci) {
                        int gn = n0 + wn + nf * 8 + t * 2 + ci;
                        int part = gn >> 9;
                        int rem = gn & 511;
                        int h_ = rem >> 6;
                        int dd = rem & 63;
                        float val = to_tf32(acc[mf][nf][ri * 2 + ci]);
                        int bh_ = b_ * NH + h_;
                        if (part == 0)      g_q[((size_t)bh_ * NTOK + n_) * DH + dd] = val;
                        else if (part == 1) g_k[((size_t)bh_ * NTOK + n_) * DH + dd] = val;
                        else                g_vt[((size_t)bh_ * DH + dd) * VP + n_] = val;
                    }
                }
            }
        }
    } else {
#pragma unroll
        for (int mf = 0; mf < 4; ++mf) {
#pragma unroll
            for (int ri = 0; ri < 2; ++ri) {
                int gm = m0 + wm + mf * 16 + g + ri * 8;
                if (gm >= MROWS) continue;
#pragma unroll
                for (int nf = 0; nf < 4; ++nf) {
                    int cbase = n0 + wn + nf * 8 + t * 2;
                    float2 o;
                    o.x = acc[mf][nf][ri * 2 + 0] + bias[cbase];
                    o.y = acc[mf][nf][ri * 2 + 1] + bias[cbase + 1];
                    *reinterpret_cast<float2*>(Cout + (size_t)gm * DIM + cbase) = o;
                }
            }
        }
    }
}

// ---------------------------------------------------------------------------
// Fused flash attention. 256 thr / 128 q-rows, 64-key tiles, 2 blocks/SM.
// K and V^T fragments via ldmatrix; Q in registers; bf16 bias; shuffle-P.
// Smem: Ks[2][64][68] + Vt[2][64][68] fp32 + Bb[128][72] bf16 = 88064 B.
// ---------------------------------------------------------------------------
namespace {
constexpr int KS_OFF = 0;                              // floats
constexpr int VS_OFF = KS_OFF + 2 * 64 * 68;
constexpr int BB_OFF = VS_OFF + 2 * 64 * 68;           // bf16 region
constexpr int FL_SMEM = BB_OFF * 4 + 128 * 72 * 2;     // 88064 bytes
}

__global__ __launch_bounds__(256, 2) void flash_attn() {
    extern __shared__ float sm[];
    __nv_bfloat16* Bbh = reinterpret_cast<__nv_bfloat16*>(sm + BB_OFF);
    const uint32_t sb = (uint32_t)__cvta_generic_to_shared(sm);

    const int bh = blockIdx.y, qt = blockIdx.x;
    const int tid = threadIdx.x;
    const int wid = tid >> 5, lane = tid & 31;
    const int g = lane >> 2, t = lane & 3;
    const float* qb = g_q + (size_t)bh * NTOK * DH;
    const float* kb = g_k + (size_t)bh * NTOK * DH;
    const float* vtb = g_vt + (size_t)bh * DH * VP;
    const __nv_bfloat16* bp = g_biasph + (size_t)(bh & 7) * NTOK * BPAD;

    // ldmatrix per-lane offset for B-fragments (stride-68 rows)
    const int laneB68 = ((lane >> 4) * 8 + (lane & 7)) * 68 + ((lane >> 3) & 1) * 4;

    auto issueKV = [&](int st, int k0) {
        float* Ks = sm + KS_OFF + st * 64 * 68;
        float* Vt = sm + VS_OFF + st * 64 * 68;
#pragma unroll
        for (int it = 0; it < 4; ++it) {
            int v = tid + it * 256;
            int row = v >> 4, c4 = (v & 15) << 2;
            int gk = k0 + row; if (gk > NTOK - 1) gk = NTOK - 1;   // bias pad masks
            cp16(&Ks[row * 68 + c4], kb + (size_t)gk * DH + c4);
            // V^T tile: row = d, cols = keys (VP=640 pad keeps reads in-bounds)
            cp16(&Vt[row * 68 + c4], vtb + (size_t)row * VP + k0 + c4);
        }
        cp_commit();
    };

    issueKV(0, 0);

    const int q0 = wid * 16;
    const int rowA = qt * 128 + q0 + g;
    const int rowB = rowA + 8;

    const float* qrA = qb + (size_t)min(rowA, NTOK - 1) * DH;
    const float* qrB = qb + (size_t)min(rowB, NTOK - 1) * DH;
    float qf[8][4];
#pragma unroll
    for (int ks = 0; ks < 8; ++ks) {
        qf[ks][0] = qrA[ks * 8 + t];
        qf[ks][1] = qrB[ks * 8 + t];
        qf[ks][2] = qrA[ks * 8 + t + 4];
        qf[ks][3] = qrB[ks * 8 + t + 4];
    }

    float accO[8][4];
#pragma unroll
    for (int df = 0; df < 8; ++df)
#pragma unroll
        for (int e = 0; e < 4; ++e) accO[df][e] = 0.f;
    float m_a = -1e30f, m_b = -1e30f, sum_a = 0.f, sum_b = 0.f;

    for (int kt = 0; kt < 10; ++kt) {
        const int k0 = kt * 64;
        const int st = kt & 1;
        const uint32_t ksAddr = sb + (uint32_t)(KS_OFF + st * 64 * 68 + laneB68) * 4;
        const uint32_t vtAddr = sb + (uint32_t)(VS_OFF + st * 64 * 68 + laneB68) * 4;

#pragma unroll
        for (int it = 0; it < 4; ++it) {
            int v = tid + it * 256;
            int row = v >> 3, c8 = (v & 7) << 3;
            int gq = qt * 128 + row; if (gq > NTOK - 1) gq = NTOK - 1;
            cp16(&Bbh[row * 72 + c8], bp + (size_t)gq * BPAD + k0 + c8);
        }
        cp_commit();
        if (kt < 9) issueKV(st ^ 1, k0 + 64);

        if (kt < 9) cp_wait<2>(); else cp_wait<1>();
        __syncthreads();

        // S = Q K^T (B-fragments via ldmatrix)
        float S[8][4];
#pragma unroll
        for (int nf = 0; nf < 8; ++nf)
#pragma unroll
            for (int e = 0; e < 4; ++e) S[nf][e] = 0.f;
#pragma unroll
        for (int ks = 0; ks < 8; ++ks) {
            const int kd4 = ks * 8 * 4;
#pragma unroll
            for (int p = 0; p < 4; ++p) {
                uint32_t bR[4];
                ldsm4(bR, ksAddr + p * (16 * 68 * 4) + kd4);
                mma8fu(S[p * 2 + 0], qf[ks], &bR[0]);
                mma8fu(S[p * 2 + 1], qf[ks], &bR[2]);
            }
        }

        if (kt < 9) cp_wait<1>(); else cp_wait<0>();
        __syncthreads();

        // scale + bias + online softmax
        float ma = -1e30f, mb = -1e30f;
#pragma unroll
        for (int nf = 0; nf < 8; ++nf) {
            int c = nf * 8 + t * 2;
            float2 bA = __bfloat1622float2(
                *reinterpret_cast<const __nv_bfloat162*>(&Bbh[(q0 + g) * 72 + c]));
            float2 bB = __bfloat1622float2(
                *reinterpret_cast<const __nv_bfloat162*>(&Bbh[(q0 + g + 8) * 72 + c]));
            S[nf][0] = S[nf][0] * SCALE + bA.x;
            S[nf][1] = S[nf][1] * SCALE + bA.y;
            S[nf][2] = S[nf][2] * SCALE + bB.x;
            S[nf][3] = S[nf][3] * SCALE + bB.y;
            ma = fmaxf(ma, fmaxf(S[nf][0], S[nf][1]));
            mb = fmaxf(mb, fmaxf(S[nf][2], S[nf][3]));
        }
        ma = fmaxf(ma, __shfl_xor_sync(0xFFFFFFFFu, ma, 1));
        ma = fmaxf(ma, __shfl_xor_sync(0xFFFFFFFFu, ma, 2));
        mb = fmaxf(mb, __shfl_xor_sync(0xFFFFFFFFu, mb, 1));
        mb = fmaxf(mb, __shfl_xor_sync(0xFFFFFFFFu, mb, 2));

        float mna = fmaxf(m_a, ma), mnb = fmaxf(m_b, mb);
        float alA = exp2f((m_a - mna) * LOG2E);
        float alB = exp2f((m_b - mnb) * LOG2E);
        m_a = mna; m_b = mnb;

        float pa = 0.f, pb = 0.f;
#pragma unroll
        for (int nf = 0; nf < 8; ++nf) {
            S[nf][0] = to_tf32(exp2f((S[nf][0] - mna) * LOG2E));
            S[nf][1] = to_tf32(exp2f((S[nf][1] - mna) * LOG2E));
            S[nf][2] = to_tf32(exp2f((S[nf][2] - mnb) * LOG2E));
            S[nf][3] = to_tf32(exp2f((S[nf][3] - mnb) * LOG2E));
            pa += S[nf][0] + S[nf][1];
            pb += S[nf][2] + S[nf][3];
        }
        sum_a = sum_a * alA + pa;
        sum_b = sum_b * alB + pb;
#pragma unroll
        for (int df = 0; df < 8; ++df) {
            accO[df][0] *= alA; accO[df][1] *= alA;
            accO[df][2] *= alB; accO[df][3] *= alB;
        }

        // O += P V ; P a-fragments via quad shuffles, V^T b-fragments via ldmatrix
        const int l0 = (lane & ~3) | (t >> 1);
        const int l1 = l0 + 2;
        const bool odd = (t & 1);
#pragma unroll
        for (int ks = 0; ks < 8; ++ks) {
            float s0A  = __shfl_sync(0xFFFFFFFFu, S[ks][0], l0);
            float s1A  = __shfl_sync(0xFFFFFFFFu, S[ks][1], l0);
            float s0B  = __shfl_sync(0xFFFFFFFFu, S[ks][2], l0);
            float s1B  = __shfl_sync(0xFFFFFFFFu, S[ks][3], l0);
            float s0A4 = __shfl_sync(0xFFFFFFFFu, S[ks][0], l1);
            float s1A4 = __shfl_sync(0xFFFFFFFFu, S[ks][1], l1);
            float s0B4 = __shfl_sync(0xFFFFFFFFu, S[ks][2], l1);
            float s1B4 = __shfl_sync(0xFFFFFFFFu, S[ks][3], l1);
            float a[4];
            a[0] = odd ? s1A : s0A;
            a[1] = odd ? s1B : s0B;
            a[2] = odd ? s1A4 : s0A4;
            a[3] = odd ? s1B4 : s0B4;
            const int kd4 = ks * 8 * 4;
#pragma unroll
            for (int p = 0; p < 4; ++p) {
                uint32_t bR[4];
                ldsm4(bR, vtAddr + p * (16 * 68 * 4) + kd4);
                mma8fu(accO[p * 2 + 0], a, &bR[0]);
                mma8fu(accO[p * 2 + 1], a, &bR[2]);
            }
        }
        __syncthreads();
    }

    sum_a += __shfl_xor_sync(0xFFFFFFFFu, sum_a, 1);
    sum_a += __shfl_xor_sync(0xFFFFFFFFu, sum_a, 2);
    sum_b += __shfl_xor_sync(0xFFFFFFFFu, sum_b, 1);
    sum_b += __shfl_xor_sync(0xFFFFFFFFu, sum_b, 2);
    const float ia = 1.f / sum_a, ib = 1.f / sum_b;

    const int b_ = bh >> 3, h_ = bh & 7;
#pragma unroll
    for (int df = 0; df < 8; ++df) {
        int col = h_ * 64 + df * 8 + t * 2;
        if (rowA < NTOK) {
            float2 o = make_float2(to_tf32(accO[df][0] * ia), to_tf32(accO[df][1] * ia));
            *reinterpret_cast<float2*>(&g_attn[(size_t)(b_ * NTOK + rowA) * DIM + col]) = o;
        }
        if (rowB < NTOK) {
            float2 o = make_float2(to_tf32(accO[df][2] * ib), to_tf32(accO[df][3] * ib));
            *reinterpret_cast<float2*>(&g_attn[(size_t)(b_ * NTOK + rowB) * DIM + col]) = o;
        }
    }
}

// ---------------------------------------------------------------------------
extern "C" void kernel_launch(void* const* d_in, const int* in_sizes, int n_in,
                              void* d_out, int out_size) {
    (void)in_sizes; (void)n_in; (void)out_size;
    const float* x          = (const float*)d_in[0];
    const float* qkv_w      = (const float*)d_in[1];
    const float* proj_w     = (const float*)d_in[2];
    const float* proj_b     = (const float*)d_in[3];
    const float* bias_table = (const float*)d_in[4];
    const int*   rel_index  = (const int*)d_in[5];
    float* out = (float*)d_out;

    static bool attr_done = false;
    if (!attr_done) {
        cudaFuncSetAttribute(gemm_tf32<0>, cudaFuncAttributeMaxDynamicSharedMemorySize, GEMM_SMEM);
        cudaFuncSetAttribute(gemm_tf32<1>, cudaFuncAttributeMaxDynamicSharedMemorySize, GEMM_SMEM);
        cudaFuncSetAttribute(flash_attn, cudaFuncAttributeMaxDynamicSharedMemorySize, FL_SMEM);
        attr_done = true;
    }

    float *xt = nullptr, *wq = nullptr, *wp = nullptr, *at = nullptr;
    cudaGetSymbolAddress((void**)&xt, g_xt);
    cudaGetSymbolAddress((void**)&wq, g_wqkv);
    cudaGetSymbolAddress((void**)&wp, g_wproj);
    cudaGetSymbolAddress((void**)&at, g_attn);

    // prep: tf32-round x and weights (hoists cvt out of GEMM mainloops)
    cvt_tf32_k<<<(MROWS * DIM / 4 + 255) / 256, 256>>>(
        (float4*)xt, (const float4*)x, MROWS * DIM / 4);
    cvt_tf32_k<<<(3 * DIM * DIM / 4 + 255) / 256, 256>>>(
        (float4*)wq, (const float4*)qkv_w, 3 * DIM * DIM / 4);
    cvt_tf32_k<<<(DIM * DIM / 4 + 255) / 256, 256>>>(
        (float4*)wp, (const float4*)proj_w, DIM * DIM / 4);
    bias_expand<<<(NTOK * BPAD + 255) / 256, 256>>>(bias_table, rel_index);

    gemm_tf32<0><<<dim3(12, 145), 256, GEMM_SMEM>>>(xt, wq, nullptr, nullptr);
    flash_attn<<<dim3(5, BH), 256, FL_SMEM>>>();
    gemm_tf32<1><<<dim3(4, 145), 256, GEMM_SMEM>>>(at, wp, proj_b, out);
}

// round 10
// speedup vs baseline: 1.1890x; 1.0138x over previous
#include <cuda_runtime.h>
#include <cuda_bf16.h>
#include <cstdint>

// ---------------------------------------------------------------------------
// Relative attention — tf32 mma.sync + ldmatrix. Round 10:
//  * fused prep kernel (cvt x/wq/wp + bias expand in one launch)
//  * gemm0 V^T epilogue transposed through smem (coalesced g_vt stores)
//  * flash: double-buffered bias, single cp.async group per tile, 2 syncs/iter
// ---------------------------------------------------------------------------

namespace {
constexpr int BATCH = 32;
constexpr int NH    = 8;
constexpr int NTOK  = 577;
constexpr int DIM   = 512;
constexpr int DH    = 64;
constexpr int BH    = BATCH * NH;        // 256
constexpr int MROWS = BATCH * NTOK;      // 18464
constexpr int BPAD  = 640;               // padded bias row stride
constexpr int VP    = 640;               // padded V^T row stride (tokens)
constexpr float SCALE = 0.125f;
constexpr float LOG2E = 1.4426950408889634f;
}

// Scratch (device globals: allocation-free contract)
__device__ float g_xt[MROWS * DIM];                    // tf32-rounded x
__device__ float g_wqkv[3 * DIM * DIM];                // tf32-rounded qkv_w
__device__ float g_wproj[DIM * DIM];                   // tf32-rounded proj_w
__device__ float g_q[BH * NTOK * DH];                  // tf32-rounded
__device__ float g_k[BH * NTOK * DH];
__device__ float g_vt[BH * DH * VP];                   // V^T [bh][d][tok]
__device__ __nv_bfloat16 g_biasph[NH * NTOK * BPAD];   // bf16 bias, pad=-1e30
__device__ float g_attn[MROWS * DIM];                  // tf32-rounded

// ---------------------------------------------------------------------------
__device__ __forceinline__ float to_tf32(float x) {
    unsigned u;
    asm("cvt.rna.tf32.f32 %0, %1;" : "=r"(u) : "f"(x));
    return __uint_as_float(u);
}

__device__ __forceinline__ void mma8u(float* d, const uint32_t* a, const uint32_t* b) {
    asm volatile(
        "mma.sync.aligned.m16n8k8.row.col.f32.tf32.tf32.f32 "
        "{%0,%1,%2,%3},{%4,%5,%6,%7},{%8,%9},{%0,%1,%2,%3};"
        : "+f"(d[0]), "+f"(d[1]), "+f"(d[2]), "+f"(d[3])
        : "r"(a[0]), "r"(a[1]), "r"(a[2]), "r"(a[3]),
          "r"(b[0]), "r"(b[1]));
}

__device__ __forceinline__ void mma8fu(float* d, const float* a, const uint32_t* b) {
    asm volatile(
        "mma.sync.aligned.m16n8k8.row.col.f32.tf32.tf32.f32 "
        "{%0,%1,%2,%3},{%4,%5,%6,%7},{%8,%9},{%0,%1,%2,%3};"
        : "+f"(d[0]), "+f"(d[1]), "+f"(d[2]), "+f"(d[3])
        : "r"(__float_as_uint(a[0])), "r"(__float_as_uint(a[1])),
          "r"(__float_as_uint(a[2])), "r"(__float_as_uint(a[3])),
          "r"(b[0]), "r"(b[1]));
}

__device__ __forceinline__ void ldsm4(uint32_t* r, uint32_t addr) {
    asm volatile("ldmatrix.sync.aligned.m8n8.x4.shared.b16 {%0,%1,%2,%3}, [%4];"
                 : "=r"(r[0]), "=r"(r[1]), "=r"(r[2]), "=r"(r[3]) : "r"(addr));
}

__device__ __forceinline__ void cp16(void* dst, const void* src) {
    unsigned d = (unsigned)__cvta_generic_to_shared(dst);
    asm volatile("cp.async.cg.shared.global [%0], [%1], 16;\n" :: "r"(d), "l"(src));
}
__device__ __forceinline__ void cp_commit() {
    asm volatile("cp.async.commit_group;\n" ::);
}
template <int N>
__device__ __forceinline__ void cp_wait() {
    asm volatile("cp.async.wait_group %0;\n" :: "n"(N));
}

// ---------------------------------------------------------------------------
// Fused prep: tf32-round x, qkv_w, proj_w; expand bias to bf16 padded layout.
// One launch; linear id partitioned across the four jobs.
// ---------------------------------------------------------------------------
namespace {
constexpr int N_X  = MROWS * DIM / 4;        // 2363392 float4s
constexpr int N_WQ = 3 * DIM * DIM / 4;      // 196608
constexpr int N_WP = DIM * DIM / 4;          // 65536
constexpr int N_B  = NTOK * BPAD;            // 369280 bias cells
constexpr int N_PREP = N_X + N_WQ + N_WP + N_B;
}

__global__ void prep_all(const float4* __restrict__ x,
                         const float4* __restrict__ wq,
                         const float4* __restrict__ wp,
                         const float* __restrict__ table,
                         const int* __restrict__ rel) {
    int i = blockIdx.x * 256 + threadIdx.x;
    if (i < N_X) {
        float4 v = x[i];
        reinterpret_cast<float4*>(g_xt)[i] =
            make_float4(to_tf32(v.x), to_tf32(v.y), to_tf32(v.z), to_tf32(v.w));
        return;
    }
    i -= N_X;
    if (i < N_WQ) {
        float4 v = wq[i];
        reinterpret_cast<float4*>(g_wqkv)[i] =
            make_float4(to_tf32(v.x), to_tf32(v.y), to_tf32(v.z), to_tf32(v.w));
        return;
    }
    i -= N_WQ;
    if (i < N_WP) {
        float4 v = wp[i];
        reinterpret_cast<float4*>(g_wproj)[i] =
            make_float4(to_tf32(v.x), to_tf32(v.y), to_tf32(v.z), to_tf32(v.w));
        return;
    }
    i -= N_WP;
    if (i < N_B) {
        int n = i / BPAD, c = i - n * BPAD;
        if (c < NTOK) {
            int r = rel[n * NTOK + c];
#pragma unroll
            for (int h = 0; h < NH; ++h)
                g_biasph[((size_t)h * NTOK + n) * BPAD + c] =
                    __float2bfloat16_rn(table[r * NH + h]);
        } else {
            __nv_bfloat16 neg = __float2bfloat16_rn(-1e30f);
#pragma unroll
            for (int h = 0; h < NH; ++h)
                g_biasph[((size_t)h * NTOK + n) * BPAD + c] = neg;
        }
    }
}

// ---------------------------------------------------------------------------
// tf32 NT GEMM, 128x128x32 tile, cp.async double-buffered, 2 blocks/SM,
// ldmatrix fragment loads.
// MODE 0: q/k scatter; V column-blocks transposed via smem -> coalesced g_vt.
// MODE 1: +bias -> Cout.
// ---------------------------------------------------------------------------
namespace {
constexpr int GSTAGE = 2 * 128 * 36;                 // floats per stage (A+B)
constexpr int GEMM_SMEM = 2 * GSTAGE * 4;            // 73728 bytes
}

template <int MODE>
__global__ __launch_bounds__(256, 2) void gemm_tf32(const float* __restrict__ A,
                                                    const float* __restrict__ Bm,
                                                    const float* __restrict__ bias,
                                                    float* __restrict__ Cout) {
    extern __shared__ float smg[];
    const int tid = threadIdx.x;
    const int lane = tid & 31, wid = tid >> 5;
    const int g = lane >> 2, t = lane & 3;
    const int m0 = blockIdx.y * 128, n0 = blockIdx.x * 128;
    const int wm = (wid >> 2) * 64, wn = (wid & 3) * 32;
    const uint32_t sb = (uint32_t)__cvta_generic_to_shared(smg);

    const int laneA = (((lane >> 3) & 1) * 8 + (lane & 7)) * 36 + (lane >> 4) * 4;
    const int laneB = ((lane >> 4) * 8 + (lane & 7)) * 36 + ((lane >> 3) & 1) * 4;

    float acc[4][4][4];
#pragma unroll
    for (int i = 0; i < 4; ++i)
#pragma unroll
        for (int j = 0; j < 4; ++j)
#pragma unroll
            for (int e = 0; e < 4; ++e) acc[i][j][e] = 0.f;

    auto issue = [&](int st, int k0) {
        float* As = smg + st * GSTAGE;
        float* Bs = As + 128 * 36;
#pragma unroll
        for (int it = 0; it < 4; ++it) {
            int v = tid + it * 256;
            int row = v >> 3, c4 = (v & 7) << 2;
            int gm = m0 + row; if (gm > MROWS - 1) gm = MROWS - 1;
            cp16(&As[row * 36 + c4], A + (size_t)gm * DIM + k0 + c4);
            int gn = n0 + row;
            cp16(&Bs[row * 36 + c4], Bm + (size_t)gn * DIM + k0 + c4);
        }
        cp_commit();
    };

    issue(0, 0);
    for (int k0 = 0; k0 < DIM; k0 += 32) {
        const int st = (k0 >> 5) & 1;
        if (k0 + 32 < DIM) { issue(st ^ 1, k0 + 32); cp_wait<1>(); }
        else cp_wait<0>();
        __syncthreads();

        const uint32_t aAddr = sb + (uint32_t)(st * GSTAGE + wm * 36 + laneA) * 4;
        const uint32_t bAddr = sb + (uint32_t)(st * GSTAGE + 128 * 36 + wn * 36 + laneB) * 4;
#pragma unroll
        for (int ks = 0; ks < 4; ++ks) {
            const int kd4 = ks * 8 * 4;
            uint32_t aR[4][4];
#pragma unroll
            for (int mf = 0; mf < 4; ++mf)
                ldsm4(aR[mf], aAddr + mf * (16 * 36 * 4) + kd4);
            uint32_t bR[2][4];
#pragma unroll
            for (int p = 0; p < 2; ++p)
                ldsm4(bR[p], bAddr + p * (16 * 36 * 4) + kd4);
#pragma unroll
            for (int p = 0; p < 2; ++p)
#pragma unroll
                for (int s = 0; s < 2; ++s) {
                    const int nf = p * 2 + s;
#pragma unroll
                    for (int mf = 0; mf < 4; ++mf)
                        mma8u(acc[mf][nf], aR[mf], &bR[p][2 * s]);
                }
        }
        __syncthreads();
    }

    if (MODE == 0) {
        if (n0 >= 1024) {
            // ---- V block: transpose 128x128 through smem, coalesced g_vt ----
            float* Ts = smg;                     // [128 cols][132 rows] 67.6KB
#pragma unroll
            for (int mf = 0; mf < 4; ++mf)
#pragma unroll
                for (int ri = 0; ri < 2; ++ri) {
                    int lr = wm + mf * 16 + g + ri * 8;
#pragma unroll
                    for (int nf = 0; nf < 4; ++nf)
#pragma unroll
                        for (int ci = 0; ci < 2; ++ci) {
                            int lc = wn + nf * 8 + t * 2 + ci;
                            Ts[lc * 132 + lr] = to_tf32(acc[mf][nf][ri * 2 + ci]);
                        }
                }
            __syncthreads();
#pragma unroll
            for (int cchunk = 0; cchunk < 16; ++cchunk) {
                int lc = cchunk * 8 + wid;
                int gn = n0 + lc;
                int rem = gn & 511;
                int h_ = rem >> 6, dd = rem & 63;
#pragma unroll
                for (int mi = 0; mi < 4; ++mi) {
                    int lr = mi * 32 + lane;
                    int gm = m0 + lr;
                    if (gm < MROWS) {
                        int b_ = gm / NTOK;
                        int n_ = gm - b_ * NTOK;
                        g_vt[(((size_t)(b_ * NH + h_)) * DH + dd) * VP + n_] =
                            Ts[lc * 132 + lr];
                    }
                }
            }
        } else {
            // ---- Q/K blocks: direct scatter (32B-coalesced) ----
#pragma unroll
            for (int mf = 0; mf < 4; ++mf) {
#pragma unroll
                for (int ri = 0; ri < 2; ++ri) {
                    int gm = m0 + wm + mf * 16 + g + ri * 8;
                    if (gm >= MROWS) continue;
                    int b_ = gm / NTOK;
                    int n_ = gm - b_ * NTOK;
#pragma unroll
                    for (int nf = 0; nf < 4; ++nf) {
#pragma unroll
                        for (int ci = 0; ci < 2; ++ci) {
                            int gn = n0 + wn + nf * 8 + t * 2 + ci;
                            int part = gn >> 9;
                            int rem = gn & 511;
                            int h_ = rem >> 6;
                            int dd = rem & 63;
                            float val = to_tf32(acc[mf][nf][ri * 2 + ci]);
                            int bh_ = b_ * NH + h_;
                            if (part == 0) g_q[((size_t)bh_ * NTOK + n_) * DH + dd] = val;
                            else           g_k[((size_t)bh_ * NTOK + n_) * DH + dd] = val;
                        }
                    }
                }
            }
        }
    } else {
#pragma unroll
        for (int mf = 0; mf < 4; ++mf) {
#pragma unroll
            for (int ri = 0; ri < 2; ++ri) {
                int gm = m0 + wm + mf * 16 + g + ri * 8;
                if (gm >= MROWS) continue;
#pragma unroll
                for (int nf = 0; nf < 4; ++nf) {
                    int cbase = n0 + wn + nf * 8 + t * 2;
                    float2 o;
                    o.x = acc[mf][nf][ri * 2 + 0] + bias[cbase];
                    o.y = acc[mf][nf][ri * 2 + 1] + bias[cbase + 1];
                    *reinterpret_cast<float2*>(Cout + (size_t)gm * DIM + cbase) = o;
                }
            }
        }
    }
}

// ---------------------------------------------------------------------------
// Fused flash attention. 256 thr / 128 q-rows, 64-key tiles, 2 blocks/SM.
// Double-buffered K/V^T AND bias; one cp.async group per tile; 2 syncs/iter.
// Smem: Ks[2][64][68] + Vt[2][64][68] fp32 + Bb[2][128][72] bf16 = 104 KB.
// ---------------------------------------------------------------------------
namespace {
constexpr int KS_OFF = 0;                              // floats
constexpr int VS_OFF = KS_OFF + 2 * 64 * 68;
constexpr int BB_OFF = VS_OFF + 2 * 64 * 68;           // bf16 region
constexpr int FL_SMEM = BB_OFF * 4 + 2 * 128 * 72 * 2; // 106496 bytes
}

__global__ __launch_bounds__(256, 2) void flash_attn() {
    extern __shared__ float sm[];
    __nv_bfloat16* Bbh = reinterpret_cast<__nv_bfloat16*>(sm + BB_OFF);
    const uint32_t sb = (uint32_t)__cvta_generic_to_shared(sm);

    const int bh = blockIdx.y, qt = blockIdx.x;
    const int tid = threadIdx.x;
    const int wid = tid >> 5, lane = tid & 31;
    const int g = lane >> 2, t = lane & 3;
    const float* qb = g_q + (size_t)bh * NTOK * DH;
    const float* kb = g_k + (size_t)bh * NTOK * DH;
    const float* vtb = g_vt + (size_t)bh * DH * VP;
    const __nv_bfloat16* bp = g_biasph + (size_t)(bh & 7) * NTOK * BPAD;

    const int laneB68 = ((lane >> 4) * 8 + (lane & 7)) * 68 + ((lane >> 3) & 1) * 4;

    // one cp.async group = bias(kt) + K(kt) + V^T(kt)
    auto issueTile = [&](int st, int kt) {
        const int k0 = kt * 64;
        float* Ks = sm + KS_OFF + st * 64 * 68;
        float* Vt = sm + VS_OFF + st * 64 * 68;
        __nv_bfloat16* Bs = Bbh + st * 128 * 72;
#pragma unroll
        for (int it = 0; it < 4; ++it) {
            int v = tid + it * 256;
            int row = v >> 3, c8 = (v & 7) << 3;
            int gq = qt * 128 + row; if (gq > NTOK - 1) gq = NTOK - 1;
            cp16(&Bs[row * 72 + c8], bp + (size_t)gq * BPAD + k0 + c8);
        }
#pragma unroll
        for (int it = 0; it < 4; ++it) {
            int v = tid + it * 256;
            int row = v >> 4, c4 = (v & 15) << 2;
            int gk = k0 + row; if (gk > NTOK - 1) gk = NTOK - 1;   // bias pad masks
            cp16(&Ks[row * 68 + c4], kb + (size_t)gk * DH + c4);
            cp16(&Vt[row * 68 + c4], vtb + (size_t)row * VP + k0 + c4);
        }
        cp_commit();
    };

    issueTile(0, 0);

    const int q0 = wid * 16;
    const int rowA = qt * 128 + q0 + g;
    const int rowB = rowA + 8;

    const float* qrA = qb + (size_t)min(rowA, NTOK - 1) * DH;
    const float* qrB = qb + (size_t)min(rowB, NTOK - 1) * DH;
    float qf[8][4];
#pragma unroll
    for (int ks = 0; ks < 8; ++ks) {
        qf[ks][0] = qrA[ks * 8 + t];
        qf[ks][1] = qrB[ks * 8 + t];
        qf[ks][2] = qrA[ks * 8 + t + 4];
        qf[ks][3] = qrB[ks * 8 + t + 4];
    }

    float accO[8][4];
#pragma unroll
    for (int df = 0; df < 8; ++df)
#pragma unroll
        for (int e = 0; e < 4; ++e) accO[df][e] = 0.f;
    float m_a = -1e30f, m_b = -1e30f, sum_a = 0.f, sum_b = 0.f;

    for (int kt = 0; kt < 10; ++kt) {
        const int st = kt & 1;
        const uint32_t ksAddr = sb + (uint32_t)(KS_OFF + st * 64 * 68 + laneB68) * 4;
        const uint32_t vtAddr = sb + (uint32_t)(VS_OFF + st * 64 * 68 + laneB68) * 4;
        const __nv_bfloat16* Bs = Bbh + st * 128 * 72;

        if (kt < 9) { issueTile(st ^ 1, kt + 1); cp_wait<1>(); }
        else cp_wait<0>();
        __syncthreads();

        // S = Q K^T
        float S[8][4];
#pragma unroll
        for (int nf = 0; nf < 8; ++nf)
#pragma unroll
            for (int e = 0; e < 4; ++e) S[nf][e] = 0.f;
#pragma unroll
        for (int ks = 0; ks < 8; ++ks) {
            const int kd4 = ks * 8 * 4;
#pragma unroll
            for (int p = 0; p < 4; ++p) {
                uint32_t bR[4];
                ldsm4(bR, ksAddr + p * (16 * 68 * 4) + kd4);
                mma8fu(S[p * 2 + 0], qf[ks], &bR[0]);
                mma8fu(S[p * 2 + 1], qf[ks], &bR[2]);
            }
        }

        // scale + bias + online softmax
        float ma = -1e30f, mb = -1e30f;
#pragma unroll
        for (int nf = 0; nf < 8; ++nf) {
            int c = nf * 8 + t * 2;
            float2 bA = __bfloat1622float2(
                *reinterpret_cast<const __nv_bfloat162*>(&Bs[(q0 + g) * 72 + c]));
            float2 bB = __bfloat1622float2(
                *reinterpret_cast<const __nv_bfloat162*>(&Bs[(q0 + g + 8) * 72 + c]));
            S[nf][0] = S[nf][0] * SCALE + bA.x;
            S[nf][1] = S[nf][1] * SCALE + bA.y;
            S[nf][2] = S[nf][2] * SCALE + bB.x;
            S[nf][3] = S[nf][3] * SCALE + bB.y;
            ma = fmaxf(ma, fmaxf(S[nf][0], S[nf][1]));
            mb = fmaxf(mb, fmaxf(S[nf][2], S[nf][3]));
        }
        ma = fmaxf(ma, __shfl_xor_sync(0xFFFFFFFFu, ma, 1));
        ma = fmaxf(ma, __shfl_xor_sync(0xFFFFFFFFu, ma, 2));
        mb = fmaxf(mb, __shfl_xor_sync(0xFFFFFFFFu, mb, 1));
        mb = fmaxf(mb, __shfl_xor_sync(0xFFFFFFFFu, mb, 2));

        float mna = fmaxf(m_a, ma), mnb = fmaxf(m_b, mb);
        float alA = exp2f((m_a - mna) * LOG2E);
        float alB = exp2f((m_b - mnb) * LOG2E);
        m_a = mna; m_b = mnb;

        float pa = 0.f, pb = 0.f;
#pragma unroll
        for (int nf = 0; nf < 8; ++nf) {
            S[nf][0] = to_tf32(exp2f((S[nf][0] - mna) * LOG2E));
            S[nf][1] = to_tf32(exp2f((S[nf][1] - mna) * LOG2E));
            S[nf][2] = to_tf32(exp2f((S[nf][2] - mnb) * LOG2E));
            S[nf][3] = to_tf32(exp2f((S[nf][3] - mnb) * LOG2E));
            pa += S[nf][0] + S[nf][1];
            pb += S[nf][2] + S[nf][3];
        }
        sum_a = sum_a * alA + pa;
        sum_b = sum_b * alB + pb;
#pragma unroll
        for (int df = 0; df < 8; ++df) {
            accO[df][0] *= alA; accO[df][1] *= alA;
            accO[df][2] *= alB; accO[df][3] *= alB;
        }

        // O += P V ; P a-fragments via quad shuffles, V^T b-fragments via ldmatrix
        const int l0 = (lane & ~3) | (t >> 1);
        const int l1 = l0 + 2;
        const bool odd = (t & 1);
#pragma unroll
        for (int ks = 0; ks < 8; ++ks) {
            float s0A  = __shfl_sync(0xFFFFFFFFu, S[ks][0], l0);
            float s1A  = __shfl_sync(0xFFFFFFFFu, S[ks][1], l0);
            float s0B  = __shfl_sync(0xFFFFFFFFu, S[ks][2], l0);
            float s1B  = __shfl_sync(0xFFFFFFFFu, S[ks][3], l0);
            float s0A4 = __shfl_sync(0xFFFFFFFFu, S[ks][0], l1);
            float s1A4 = __shfl_sync(0xFFFFFFFFu, S[ks][1], l1);
            float s0B4 = __shfl_sync(0xFFFFFFFFu, S[ks][2], l1);
            float s1B4 = __shfl_sync(0xFFFFFFFFu, S[ks][3], l1);
            float a[4];
            a[0] = odd ? s1A : s0A;
            a[1] = odd ? s1B : s0B;
            a[2] = odd ? s1A4 : s0A4;
            a[3] = odd ? s1B4 : s0B4;
            const int kd4 = ks * 8 * 4;
#pragma unroll
            for (int p = 0; p < 4; ++p) {
                uint32_t bR[4];
                ldsm4(bR, vtAddr + p * (16 * 68 * 4) + kd4);
                mma8fu(accO[p * 2 + 0], a, &bR[0]);
                mma8fu(accO[p * 2 + 1], a, &bR[2]);
            }
        }
        __syncthreads();
    }

    sum_a += __shfl_xor_sync(0xFFFFFFFFu, sum_a, 1);
    sum_a += __shfl_xor_sync(0xFFFFFFFFu, sum_a, 2);
    sum_b += __shfl_xor_sync(0xFFFFFFFFu, sum_b, 1);
    sum_b += __shfl_xor_sync(0xFFFFFFFFu, sum_b, 2);
    const float ia = 1.f / sum_a, ib = 1.f / sum_b;

    const int b_ = bh >> 3, h_ = bh & 7;
#pragma unroll
    for (int df = 0; df < 8; ++df) {
        int col = h_ * 64 + df * 8 + t * 2;
        if (rowA < NTOK) {
            float2 o = make_float2(to_tf32(accO[df][0] * ia), to_tf32(accO[df][1] * ia));
            *reinterpret_cast<float2*>(&g_attn[(size_t)(b_ * NTOK + rowA) * DIM + col]) = o;
        }
        if (rowB < NTOK) {
            float2 o = make_float2(to_tf32(accO[df][2] * ib), to_tf32(accO[df][3] * ib));
            *reinterpret_cast<float2*>(&g_attn[(size_t)(b_ * NTOK + rowB) * DIM + col]) = o;
        }
    }
}

// ---------------------------------------------------------------------------
extern "C" void kernel_launch(void* const* d_in, const int* in_sizes, int n_in,
                              void* d_out, int out_size) {
    (void)in_sizes; (void)n_in; (void)out_size;
    const float* x          = (const float*)d_in[0];
    const float* qkv_w      = (const float*)d_in[1];
    const float* proj_w     = (const float*)d_in[2];
    const float* proj_b     = (const float*)d_in[3];
    const float* bias_table = (const float*)d_in[4];
    const int*   rel_index  = (const int*)d_in[5];
    float* out = (float*)d_out;

    static bool attr_done = false;
    if (!attr_done) {
        cudaFuncSetAttribute(gemm_tf32<0>, cudaFuncAttributeMaxDynamicSharedMemorySize, GEMM_SMEM);
        cudaFuncSetAttribute(gemm_tf32<1>, cudaFuncAttributeMaxDynamicSharedMemorySize, GEMM_SMEM);
        cudaFuncSetAttribute(flash_attn, cudaFuncAttributeMaxDynamicSharedMemorySize, FL_SMEM);
        attr_done = true;
    }

    float *xt = nullptr, *wq = nullptr, *wp = nullptr, *at = nullptr;
    cudaGetSymbolAddress((void**)&xt, g_xt);
    cudaGetSymbolAddress((void**)&wq, g_wqkv);
    cudaGetSymbolAddress((void**)&wp, g_wproj);
    cudaGetSymbolAddress((void**)&at, g_attn);

    prep_all<<<(N_PREP + 255) / 256, 256>>>(
        (const float4*)x, (const float4*)qkv_w, (const float4*)proj_w,
        bias_table, rel_index);

    gemm_tf32<0><<<dim3(12, 145), 256, GEMM_SMEM>>>(xt, wq, nullptr, nullptr);
    flash_attn<<<dim3(5, BH), 256, FL_SMEM>>>();
    gemm_tf32<1><<<dim3(4, 145), 256, GEMM_SMEM>>>(at, wp, proj_b, out);
}